// round 3
// baseline (speedup 1.0000x reference)
#include <cuda_runtime.h>
#include <cstdint>
#include <cstring>
#include <math.h>

// Shapes
#define BATCH 64
#define ED 512
#define RES 28
#define HW 784           // 28*28
#define WS 7
#define NWIN 16          // 4*4 windows per image
#define NW_TOT 1024      // BATCH*NWIN
#define NH 8
#define KD 16
#define DHEAD 64         // AR*KD
#define QKV_OUT 96       // 2*KD + DHEAD
#define NTOK 49          // WS*WS

#define TOT 25690112     // 64*512*784
#define HID_TOT 51380224 // 64*1024*784

// Scratch (device globals; no allocations allowed)
__device__ float g_a[TOT];
__device__ float g_b[TOT];
__device__ float g_c[TOT];
__device__ float g_h[HID_TOT];

__device__ __forceinline__ float hswish(float x) {
    return x * fminf(fmaxf(x + 3.f, 0.f), 6.f) * (1.f / 6.f);
}

typedef unsigned long long ull;

__device__ __forceinline__ void fma2(ull& d, ull a, ull b) {
    asm("fma.rn.f32x2 %0, %1, %2, %0;" : "+l"(d) : "l"(a), "l"(b));
}
__device__ __forceinline__ float2 u2f(ull u) {
    float2 f; memcpy(&f, &u, 8); return f;
}

// ---------------------------------------------------------------------------
// Depthwise 3x3 conv (SAME) + residual:  out = x + dwconv(x)
// ---------------------------------------------------------------------------
__global__ void __launch_bounds__(256) dwconv_res_kernel(
                                  const float* __restrict__ x,
                                  const float* __restrict__ w,
                                  const float* __restrict__ bias,
                                  float* __restrict__ out)
{
    int bc = blockIdx.y;
    int c = bc & (ED - 1);
    int pos = blockIdx.x * 256 + threadIdx.x;
    if (pos >= HW) return;
    int h = pos / RES, ww = pos % RES;
    const float* xp = x + (size_t)bc * HW;
    const float* wp = w + c * 9;
    float acc = bias[c];
#pragma unroll
    for (int dy = 0; dy < 3; dy++) {
        int yy = h + dy - 1;
        if (yy < 0 || yy >= RES) continue;
#pragma unroll
        for (int dx = 0; dx < 3; dx++) {
            int xx = ww + dx - 1;
            if (xx < 0 || xx >= RES) continue;
            acc += xp[yy * RES + xx] * wp[dy * 3 + dx];
        }
    }
    out[(size_t)bc * HW + pos] = xp[pos] + acc;
}

// ---------------------------------------------------------------------------
// Batched fp32 GEMM with packed f32x2 FMA: C[z] = A @ Bin[z]
//   A: [M,K] row-major (weights), Bin: [Z][K][N], C: [Z][M][N]
// Block tile 128x64, K-step 16, 256 threads, 8x4 register tile per thread.
// A tile stored duplicated in smem: one LDS.128 -> two broadcast f32x2 operands.
// ---------------------------------------------------------------------------
#define AS_STRIDE 260   // floats per k-row of As2 (16B-aligned, low bank conflict)

template<bool HSW_IN, bool HSW_OUT, bool RESID>
__global__ void __launch_bounds__(256) gemm2_kernel(
                            const float* __restrict__ A,
                            const float* __restrict__ Bin,
                            const float* __restrict__ bias,
                            const float* __restrict__ resid,
                            float* __restrict__ C,
                            int M, int N, int K)
{
    __shared__ float As2[16 * AS_STRIDE];  // duplicated: As2[k][2m]=As2[k][2m+1]=A val
    __shared__ float Bs[16 * 64];
    int z = blockIdx.z;
    int m0 = blockIdx.y * 128;
    int n0 = blockIdx.x * 64;
    const float* Bz = Bin + (size_t)z * K * N;
    int t = threadIdx.x;
    int tx = t & 15, ty = t >> 4;
    int ka = t & 15, ma = t >> 4;   // A-load mapping
    bool full_n = (n0 + 64 <= N);

    ull acc[8][2];
#pragma unroll
    for (int i = 0; i < 8; i++) { acc[i][0] = 0ull; acc[i][1] = 0ull; }

    for (int k0 = 0; k0 < K; k0 += 16) {
        // A tile: 128 rows x 16 k, duplicated store
#pragma unroll
        for (int i = 0; i < 8; i++) {
            int m = ma + i * 16;
            float a = A[(size_t)(m0 + m) * K + (k0 + ka)];
            float2 d = make_float2(a, a);
            *reinterpret_cast<float2*>(&As2[ka * AS_STRIDE + 2 * m]) = d;
        }
        // B tile: 16 k x 64 n
        if (full_n) {
#pragma unroll
            for (int i = 0; i < 4; i++) {
                int lin = t + i * 256;
                int kb = lin >> 6, n = lin & 63;
                float v = Bz[(size_t)(k0 + kb) * N + (n0 + n)];
                if (HSW_IN) v = hswish(v);
                Bs[kb * 64 + n] = v;
            }
        } else {
#pragma unroll
            for (int i = 0; i < 4; i++) {
                int lin = t + i * 256;
                int kb = lin >> 6, n = lin & 63;
                float v = 0.f;
                if (n0 + n < N) v = Bz[(size_t)(k0 + kb) * N + (n0 + n)];
                if (HSW_IN) v = hswish(v);
                Bs[kb * 64 + n] = v;
            }
        }
        __syncthreads();
#pragma unroll
        for (int kk = 0; kk < 16; kk++) {
            ulonglong2 b = *reinterpret_cast<const ulonglong2*>(&Bs[kk * 64 + tx * 4]);
#pragma unroll
            for (int i = 0; i < 4; i++) {
                ulonglong2 a = *reinterpret_cast<const ulonglong2*>(
                    &As2[kk * AS_STRIDE + ty * 16 + i * 4]);
                fma2(acc[2 * i    ][0], a.x, b.x);
                fma2(acc[2 * i    ][1], a.x, b.y);
                fma2(acc[2 * i + 1][0], a.y, b.x);
                fma2(acc[2 * i + 1][1], a.y, b.y);
            }
        }
        __syncthreads();
    }

#pragma unroll
    for (int i = 0; i < 8; i++) {
        int m = m0 + ty * 8 + i;
        float bval = bias[m];
        float2 p0 = u2f(acc[i][0]);
        float2 p1 = u2f(acc[i][1]);
        float vals[4] = {p0.x, p0.y, p1.x, p1.y};
#pragma unroll
        for (int j = 0; j < 4; j++) {
            int n = n0 + tx * 4 + j;
            if (n < N) {
                float v = vals[j] + bval;
                if (HSW_OUT) v = hswish(v);
                size_t o = (size_t)z * M * N + (size_t)m * N + n;
                if (RESID) v += resid[o];
                C[o] = v;
            }
        }
    }
}

// ---------------------------------------------------------------------------
// Cascaded window attention. One block per window (1024 blocks, 256 threads).
// ---------------------------------------------------------------------------
#define ATTN_SMEM_FLOATS (64*49 + 96*49 + 16*49 + 49*49 + 96*64 + 96 + 49)
#define ATTN_SMEM_BYTES  (ATTN_SMEM_FLOATS * 4)

__global__ void __launch_bounds__(256) attn_kernel(
                            const float* __restrict__ xin,
                            const float* __restrict__ qkv_w,   // [8,96,64]
                            const float* __restrict__ qkv_b,   // [8,96]
                            const float* __restrict__ w7, const float* __restrict__ b7,
                            const float* __restrict__ w5, const float* __restrict__ b5,
                            const float* __restrict__ w3, const float* __restrict__ b3,
                            const float* __restrict__ attn_bias, // [8,49]
                            float* __restrict__ out)             // [1024,512,49]
{
    extern __shared__ float smem[];
    float* sp  = smem;                 // [64][49]
    float* y   = sp  + 64 * 49;        // [96][49]  (q|k|v)
    float* qc  = y   + 96 * 49;        // [16][49]
    float* att = qc  + 16 * 49;        // [49][49]
    float* wsm = att + 49 * 49;        // [96*64]
    float* bsm = wsm + 96 * 64;        // [96]
    float* bia = bsm + 96;             // [49]

    int w = blockIdx.x;
    int b = w >> 4, wy = (w >> 2) & 3, wx = w & 3;
    int t = threadIdx.x;
    const float* xb = xin + (size_t)b * ED * HW;

    for (int head = 0; head < NH; head++) {
        for (int i = t; i < QKV_OUT * DHEAD; i += 256) wsm[i] = qkv_w[head * QKV_OUT * DHEAD + i];
        if (t < QKV_OUT) bsm[t] = qkv_b[head * QKV_OUT + t];
        if (t < NTOK)    bia[t] = attn_bias[head * NTOK + t];
        for (int i = t; i < DHEAD * NTOK; i += 256) {
            int c = i / NTOK, n = i % NTOK;
            int iy = n / WS, ix = n % WS;
            float xv = xb[(size_t)(head * DHEAD + c) * HW + (wy * WS + iy) * RES + (wx * WS + ix)];
            sp[i] = (head == 0) ? xv : sp[i] + xv;
        }
        __syncthreads();
        // y = Wqkv @ sp + b   [96,49]
        for (int o = t; o < QKV_OUT * NTOK; o += 256) {
            int m = o / NTOK, n = o % NTOK;
            float acc = bsm[m];
            const float* wr = &wsm[m * DHEAD];
#pragma unroll 8
            for (int c = 0; c < DHEAD; c++) acc += wr[c] * sp[c * NTOK + n];
            y[o] = acc;
        }
        __syncthreads();
        // depthwise conv on q (rows 0..15 of y)
        int ksz; const float* dw; const float* db;
        if (head == 0)      { ksz = 7; dw = w7; db = b7; }
        else if (head == 1) { ksz = 5; dw = w5; db = b5; }
        else                { ksz = 3; dw = w3 + (head - 2) * KD * 9; db = b3 + (head - 2) * KD; }
        int pad = ksz >> 1;
        for (int o = t; o < KD * NTOK; o += 256) {
            int c = o / NTOK, n = o % NTOK;
            int iy = n / WS, ix = n % WS;
            float acc = db[c];
            for (int dy = 0; dy < ksz; dy++) {
                int yy = iy + dy - pad;
                if (yy < 0 || yy >= WS) continue;
                for (int dx = 0; dx < ksz; dx++) {
                    int xx = ix + dx - pad;
                    if (xx < 0 || xx >= WS) continue;
                    acc += y[c * NTOK + yy * WS + xx] * dw[c * ksz * ksz + dy * ksz + dx];
                }
            }
            qc[o] = acc;
        }
        __syncthreads();
        for (int o = t; o < NTOK * NTOK; o += 256) {
            int n = o / NTOK, m = o % NTOK;
            float acc = 0.f;
#pragma unroll
            for (int c = 0; c < KD; c++) acc += qc[c * NTOK + n] * y[(KD + c) * NTOK + m];
            int ny = n / WS, nx = n % WS, my = m / WS, mx = m % WS;
            att[o] = acc * 0.25f + bia[abs(ny - my) * WS + abs(nx - mx)];
        }
        __syncthreads();
        if (t < NTOK) {
            float mx = -1e30f;
            for (int m = 0; m < NTOK; m++) mx = fmaxf(mx, att[t * NTOK + m]);
            float s = 0.f;
            for (int m = 0; m < NTOK; m++) { float e = expf(att[t * NTOK + m] - mx); att[t * NTOK + m] = e; s += e; }
            float inv = 1.f / s;
            for (int m = 0; m < NTOK; m++) att[t * NTOK + m] *= inv;
        }
        __syncthreads();
        float* outw = out + ((size_t)w * (NH * DHEAD) + head * DHEAD) * NTOK;
        for (int o = t; o < DHEAD * NTOK; o += 256) {
            int d = o / NTOK, n = o % NTOK;
            float acc = 0.f;
#pragma unroll 7
            for (int m = 0; m < NTOK; m++) acc += y[(2 * KD + d) * NTOK + m] * att[n * NTOK + m];
            outw[d * NTOK + n] = acc;
            sp[o] = acc;
        }
        __syncthreads();
    }
}

// ---------------------------------------------------------------------------
// Window merge + residual
// ---------------------------------------------------------------------------
__global__ void __launch_bounds__(256) merge_res_kernel(
                                 const float* __restrict__ resid,
                                 const float* __restrict__ proj,
                                 float* __restrict__ out)
{
    size_t idx = (size_t)blockIdx.x * 256 + threadIdx.x;
    if (idx >= (size_t)TOT) return;
    int pos = (int)(idx % HW);
    int c = (int)((idx / HW) % ED);
    int b = (int)(idx / ((size_t)HW * ED));
    int h = pos / RES, x = pos % RES;
    int wy = h / WS, iy = h % WS, wx = x / WS, ix = x % WS;
    int win = (b * 4 + wy) * 4 + wx;
    out[idx] = resid[idx] + proj[((size_t)win * ED + c) * NTOK + iy * WS + ix];
}

// ---------------------------------------------------------------------------
extern "C" void kernel_launch(void* const* d_in, const int* in_sizes, int n_in,
                              void* d_out, int out_size)
{
    const float* x        = (const float*)d_in[0];
    const float* dw0_w    = (const float*)d_in[1];
    const float* dw0_b    = (const float*)d_in[2];
    const float* ffn0_w1  = (const float*)d_in[3];
    const float* ffn0_b1  = (const float*)d_in[4];
    const float* ffn0_w2  = (const float*)d_in[5];
    const float* ffn0_b2  = (const float*)d_in[6];
    const float* qkv_w    = (const float*)d_in[7];
    const float* qkv_b    = (const float*)d_in[8];
    const float* dwq_w7   = (const float*)d_in[9];
    const float* dwq_b7   = (const float*)d_in[10];
    const float* dwq_w5   = (const float*)d_in[11];
    const float* dwq_b5   = (const float*)d_in[12];
    const float* dwq_w3   = (const float*)d_in[13];
    const float* dwq_b3   = (const float*)d_in[14];
    const float* attn_bias= (const float*)d_in[15];
    const float* proj_w   = (const float*)d_in[16];
    const float* proj_b   = (const float*)d_in[17];
    const float* dw1_w    = (const float*)d_in[18];
    const float* dw1_b    = (const float*)d_in[19];
    const float* ffn1_w1  = (const float*)d_in[20];
    const float* ffn1_b1  = (const float*)d_in[21];
    const float* ffn1_w2  = (const float*)d_in[22];
    const float* ffn1_b2  = (const float*)d_in[23];

    float *pa, *pb, *pc, *ph;
    cudaGetSymbolAddress((void**)&pa, g_a);
    cudaGetSymbolAddress((void**)&pb, g_b);
    cudaGetSymbolAddress((void**)&pc, g_c);
    cudaGetSymbolAddress((void**)&ph, g_h);

    cudaFuncSetAttribute(attn_kernel, cudaFuncAttributeMaxDynamicSharedMemorySize, ATTN_SMEM_BYTES);

    dim3 dwgrid((HW + 255) / 256, BATCH * ED);

    // Stage 1: a = x + dwconv(x)
    dwconv_res_kernel<<<dwgrid, 256>>>(x, dw0_w, dw0_b, pa);
    // Stage 2: h = hswish(W1 a + b1); b = a + W2 h + b2
    gemm2_kernel<false, true, false><<<dim3(13, 8, BATCH), 256>>>(ffn0_w1, pa, ffn0_b1, nullptr, ph, 1024, HW, 512);
    gemm2_kernel<false, false, true><<<dim3(13, 4, BATCH), 256>>>(ffn0_w2, ph, ffn0_b2, pa, pb, 512, HW, 1024);
    // Stage 3: cascaded window attention -> c [1024,512,49]
    attn_kernel<<<NW_TOT, 256, ATTN_SMEM_BYTES>>>(pb, qkv_w, qkv_b, dwq_w7, dwq_b7, dwq_w5, dwq_b5,
                                                  dwq_w3, dwq_b3, attn_bias, pc);
    // Stage 4: proj on hswish(c) -> a [1024,512,49]
    gemm2_kernel<true, false, false><<<dim3(1, 4, NW_TOT), 256>>>(proj_w, pc, proj_b, nullptr, pa, 512, NTOK, 512);
    // Stage 5: c = b + merge(a)
    merge_res_kernel<<<(TOT + 255) / 256, 256>>>(pb, pa, pc);
    // Stage 6: b = c + dwconv(c)
    dwconv_res_kernel<<<dwgrid, 256>>>(pc, dw1_w, dw1_b, pb);
    // Stage 7: h = hswish(W1' b + b1'); out = b + W2' h + b2'
    gemm2_kernel<false, true, false><<<dim3(13, 8, BATCH), 256>>>(ffn1_w1, pb, ffn1_b1, nullptr, ph, 1024, HW, 512);
    gemm2_kernel<false, false, true><<<dim3(13, 4, BATCH), 256>>>(ffn1_w2, ph, ffn1_b2, pb, (float*)d_out, 512, HW, 1024);
}

// round 4
// speedup vs baseline: 2.1143x; 2.1143x over previous
#include <cuda_runtime.h>
#include <cuda_bf16.h>
#include <cstdint>
#include <cstring>
#include <math.h>

// Shapes
#define BATCH 64
#define ED 512
#define RES 28
#define HW 784           // 28*28
#define WS 7
#define NWIN 16
#define NW_TOT 1024
#define NH 8
#define KD 16
#define DHEAD 64
#define QKV_OUT 96
#define NTOK 49

#define TOT 25690112     // 64*512*784
#define HID_TOT 51380224 // 64*1024*784

// Scratch (device globals; no allocations allowed)
__device__ float g_a[TOT];
__device__ float g_b[TOT];
__device__ float g_c[TOT];
__device__ float g_h[HID_TOT];

__device__ __forceinline__ float hswish(float x) {
    return x * fminf(fmaxf(x + 3.f, 0.f), 6.f) * (1.f / 6.f);
}

// ---------------------------------------------------------------------------
// Depthwise 3x3 conv (SAME) + residual
// ---------------------------------------------------------------------------
__global__ void __launch_bounds__(256) dwconv_res_kernel(
                                  const float* __restrict__ x,
                                  const float* __restrict__ w,
                                  const float* __restrict__ bias,
                                  float* __restrict__ out)
{
    int bc = blockIdx.y;
    int c = bc & (ED - 1);
    int pos = blockIdx.x * 256 + threadIdx.x;
    if (pos >= HW) return;
    int h = pos / RES, ww = pos % RES;
    const float* xp = x + (size_t)bc * HW;
    const float* wp = w + c * 9;
    float acc = bias[c];
#pragma unroll
    for (int dy = 0; dy < 3; dy++) {
        int yy = h + dy - 1;
        if (yy < 0 || yy >= RES) continue;
#pragma unroll
        for (int dx = 0; dx < 3; dx++) {
            int xx = ww + dx - 1;
            if (xx < 0 || xx >= RES) continue;
            acc += xp[yy * RES + xx] * wp[dy * 3 + dx];
        }
    }
    out[(size_t)bc * HW + pos] = xp[pos] + acc;
}

// ---------------------------------------------------------------------------
// Tensor-core GEMM (bf16-split, fp32 accumulate): C[z] = A @ Bin[z]
//   A: [M,K] weights row-major, Bin: [Z][K][N], C: [Z][M][N]
// CTA tile 128x64, K-chunk 32. 8 warps: 4 along M x 2 along N, warp tile 32x32.
// mma.sync.m16n8k16.bf16; split x = hi+lo, compute hh + hl + lh.
// ---------------------------------------------------------------------------
#define BM 128
#define BN 64
#define KC 32
#define KCP 34   // padded row stride (bf16 elems) -> conflict-free frag loads

__device__ __forceinline__ void mma_bf16(float* c, uint32_t a0, uint32_t a1,
                                         uint32_t a2, uint32_t a3,
                                         uint32_t b0, uint32_t b1)
{
    asm volatile(
        "mma.sync.aligned.m16n8k16.row.col.f32.bf16.bf16.f32 "
        "{%0,%1,%2,%3}, {%4,%5,%6,%7}, {%8,%9}, {%0,%1,%2,%3};\n"
        : "+f"(c[0]), "+f"(c[1]), "+f"(c[2]), "+f"(c[3])
        : "r"(a0), "r"(a1), "r"(a2), "r"(a3), "r"(b0), "r"(b1));
}

template<bool HSW_IN, bool HSW_OUT, bool RESID>
__global__ void __launch_bounds__(256) gemm_tc_kernel(
                            const float* __restrict__ A,
                            const float* __restrict__ Bin,
                            const float* __restrict__ bias,
                            const float* __restrict__ resid,
                            float* __restrict__ C,
                            int M, int N, int K)
{
    __shared__ __nv_bfloat16 Ah[BM * KCP];
    __shared__ __nv_bfloat16 Al[BM * KCP];
    __shared__ __nv_bfloat16 Bh[BN * KCP];
    __shared__ __nv_bfloat16 Bl[BN * KCP];

    int z = blockIdx.z;
    int m0 = blockIdx.y * BM;
    int n0 = blockIdx.x * BN;
    const float* Bz = Bin + (size_t)z * K * N;

    int t = threadIdx.x;
    int warp = t >> 5, lane = t & 31;
    int wm = warp & 3, wn = warp >> 2;       // 4 warps along M, 2 along N
    int m0w = wm * 32, n0w = wn * 32;
    int g = lane >> 2, tig = lane & 3;       // groupID, thread-in-group

    float acc[2][4][4];
#pragma unroll
    for (int i = 0; i < 2; i++)
#pragma unroll
        for (int j = 0; j < 4; j++)
#pragma unroll
            for (int q = 0; q < 4; q++) acc[i][j][q] = 0.f;

    for (int k0 = 0; k0 < K; k0 += KC) {
        // Stage A tile (128 x 32), split to hi/lo bf16
#pragma unroll
        for (int it = 0; it < 16; it++) {
            int lin = t + it * 256;          // 4096 elements
            int k = lin & 31, m = lin >> 5;
            float v = A[(size_t)(m0 + m) * K + (k0 + k)];
            __nv_bfloat16 h = __float2bfloat16_rn(v);
            float hf = __bfloat162float(h);
            __nv_bfloat16 l = __float2bfloat16_rn(v - hf);
            Ah[m * KCP + k] = h;
            Al[m * KCP + k] = l;
        }
        // Stage B tile transposed (Bs[n][k]), split to hi/lo bf16
#pragma unroll
        for (int it = 0; it < 8; it++) {
            int lin = t + it * 256;          // 2048 elements
            int n = lin & 63, kb = lin >> 6;
            float v = 0.f;
            if (n0 + n < N) v = Bz[(size_t)(k0 + kb) * N + (n0 + n)];
            if (HSW_IN) v = hswish(v);
            __nv_bfloat16 h = __float2bfloat16_rn(v);
            float hf = __bfloat162float(h);
            __nv_bfloat16 l = __float2bfloat16_rn(v - hf);
            Bh[n * KCP + kb] = h;
            Bl[n * KCP + kb] = l;
        }
        __syncthreads();

#pragma unroll
        for (int kk = 0; kk < KC; kk += 16) {
            // A fragments: 2 m-tiles, hi+lo
            uint32_t ah[2][4], al[2][4];
#pragma unroll
            for (int i = 0; i < 2; i++) {
                int mb = m0w + i * 16;
                ah[i][0] = *(const uint32_t*)&Ah[(mb + g) * KCP + kk + tig * 2];
                ah[i][1] = *(const uint32_t*)&Ah[(mb + g + 8) * KCP + kk + tig * 2];
                ah[i][2] = *(const uint32_t*)&Ah[(mb + g) * KCP + kk + 8 + tig * 2];
                ah[i][3] = *(const uint32_t*)&Ah[(mb + g + 8) * KCP + kk + 8 + tig * 2];
                al[i][0] = *(const uint32_t*)&Al[(mb + g) * KCP + kk + tig * 2];
                al[i][1] = *(const uint32_t*)&Al[(mb + g + 8) * KCP + kk + tig * 2];
                al[i][2] = *(const uint32_t*)&Al[(mb + g) * KCP + kk + 8 + tig * 2];
                al[i][3] = *(const uint32_t*)&Al[(mb + g + 8) * KCP + kk + 8 + tig * 2];
            }
            // B fragments: 4 n-tiles, hi+lo
            uint32_t bh[4][2], bl[4][2];
#pragma unroll
            for (int j = 0; j < 4; j++) {
                int nb = n0w + j * 8;
                bh[j][0] = *(const uint32_t*)&Bh[(nb + g) * KCP + kk + tig * 2];
                bh[j][1] = *(const uint32_t*)&Bh[(nb + g) * KCP + kk + 8 + tig * 2];
                bl[j][0] = *(const uint32_t*)&Bl[(nb + g) * KCP + kk + tig * 2];
                bl[j][1] = *(const uint32_t*)&Bl[(nb + g) * KCP + kk + 8 + tig * 2];
            }
#pragma unroll
            for (int i = 0; i < 2; i++)
#pragma unroll
                for (int j = 0; j < 4; j++) {
                    mma_bf16(acc[i][j], ah[i][0], ah[i][1], ah[i][2], ah[i][3],
                             bh[j][0], bh[j][1]);
                    mma_bf16(acc[i][j], ah[i][0], ah[i][1], ah[i][2], ah[i][3],
                             bl[j][0], bl[j][1]);
                    mma_bf16(acc[i][j], al[i][0], al[i][1], al[i][2], al[i][3],
                             bh[j][0], bh[j][1]);
                }
        }
        __syncthreads();
    }

    // Epilogue: D[g][tig*2], D[g][tig*2+1], D[g+8][tig*2], D[g+8][tig*2+1]
#pragma unroll
    for (int i = 0; i < 2; i++) {
#pragma unroll
        for (int j = 0; j < 4; j++) {
            int r0 = m0 + m0w + i * 16 + g;
            int r1 = r0 + 8;
            int cb = n0 + n0w + j * 8 + tig * 2;
            float b0v = bias[r0], b1v = bias[r1];
#pragma unroll
            for (int q = 0; q < 2; q++) {
                int n = cb + q;
                if (n < N) {
                    float v = acc[i][j][q] + b0v;
                    if (HSW_OUT) v = hswish(v);
                    size_t o = (size_t)z * M * N + (size_t)r0 * N + n;
                    if (RESID) v += resid[o];
                    C[o] = v;
                    float v2 = acc[i][j][q + 2] + b1v;
                    if (HSW_OUT) v2 = hswish(v2);
                    size_t o2 = (size_t)z * M * N + (size_t)r1 * N + n;
                    if (RESID) v2 += resid[o2];
                    C[o2] = v2;
                }
            }
        }
    }
}

// ---------------------------------------------------------------------------
// Cascaded window attention (unchanged)
// ---------------------------------------------------------------------------
#define ATTN_SMEM_FLOATS (64*49 + 96*49 + 16*49 + 49*49 + 96*64 + 96 + 49)
#define ATTN_SMEM_BYTES  (ATTN_SMEM_FLOATS * 4)

__global__ void __launch_bounds__(256) attn_kernel(
                            const float* __restrict__ xin,
                            const float* __restrict__ qkv_w,
                            const float* __restrict__ qkv_b,
                            const float* __restrict__ w7, const float* __restrict__ b7,
                            const float* __restrict__ w5, const float* __restrict__ b5,
                            const float* __restrict__ w3, const float* __restrict__ b3,
                            const float* __restrict__ attn_bias,
                            float* __restrict__ out)
{
    extern __shared__ float smem[];
    float* sp  = smem;
    float* y   = sp  + 64 * 49;
    float* qc  = y   + 96 * 49;
    float* att = qc  + 16 * 49;
    float* wsm = att + 49 * 49;
    float* bsm = wsm + 96 * 64;
    float* bia = bsm + 96;

    int w = blockIdx.x;
    int b = w >> 4, wy = (w >> 2) & 3, wx = w & 3;
    int t = threadIdx.x;
    const float* xb = xin + (size_t)b * ED * HW;

    for (int head = 0; head < NH; head++) {
        for (int i = t; i < QKV_OUT * DHEAD; i += 256) wsm[i] = qkv_w[head * QKV_OUT * DHEAD + i];
        if (t < QKV_OUT) bsm[t] = qkv_b[head * QKV_OUT + t];
        if (t < NTOK)    bia[t] = attn_bias[head * NTOK + t];
        for (int i = t; i < DHEAD * NTOK; i += 256) {
            int c = i / NTOK, n = i % NTOK;
            int iy = n / WS, ix = n % WS;
            float xv = xb[(size_t)(head * DHEAD + c) * HW + (wy * WS + iy) * RES + (wx * WS + ix)];
            sp[i] = (head == 0) ? xv : sp[i] + xv;
        }
        __syncthreads();
        for (int o = t; o < QKV_OUT * NTOK; o += 256) {
            int m = o / NTOK, n = o % NTOK;
            float acc = bsm[m];
            const float* wr = &wsm[m * DHEAD];
#pragma unroll 8
            for (int c = 0; c < DHEAD; c++) acc += wr[c] * sp[c * NTOK + n];
            y[o] = acc;
        }
        __syncthreads();
        int ksz; const float* dw; const float* db;
        if (head == 0)      { ksz = 7; dw = w7; db = b7; }
        else if (head == 1) { ksz = 5; dw = w5; db = b5; }
        else                { ksz = 3; dw = w3 + (head - 2) * KD * 9; db = b3 + (head - 2) * KD; }
        int pad = ksz >> 1;
        for (int o = t; o < KD * NTOK; o += 256) {
            int c = o / NTOK, n = o % NTOK;
            int iy = n / WS, ix = n % WS;
            float acc = db[c];
            for (int dy = 0; dy < ksz; dy++) {
                int yy = iy + dy - pad;
                if (yy < 0 || yy >= WS) continue;
                for (int dx = 0; dx < ksz; dx++) {
                    int xx = ix + dx - pad;
                    if (xx < 0 || xx >= WS) continue;
                    acc += y[c * NTOK + yy * WS + xx] * dw[c * ksz * ksz + dy * ksz + dx];
                }
            }
            qc[o] = acc;
        }
        __syncthreads();
        for (int o = t; o < NTOK * NTOK; o += 256) {
            int n = o / NTOK, m = o % NTOK;
            float acc = 0.f;
#pragma unroll
            for (int c = 0; c < KD; c++) acc += qc[c * NTOK + n] * y[(KD + c) * NTOK + m];
            int ny = n / WS, nx = n % WS, my = m / WS, mx = m % WS;
            att[o] = acc * 0.25f + bia[abs(ny - my) * WS + abs(nx - mx)];
        }
        __syncthreads();
        if (t < NTOK) {
            float mx = -1e30f;
            for (int m = 0; m < NTOK; m++) mx = fmaxf(mx, att[t * NTOK + m]);
            float s = 0.f;
            for (int m = 0; m < NTOK; m++) { float e = expf(att[t * NTOK + m] - mx); att[t * NTOK + m] = e; s += e; }
            float inv = 1.f / s;
            for (int m = 0; m < NTOK; m++) att[t * NTOK + m] *= inv;
        }
        __syncthreads();
        float* outw = out + ((size_t)w * (NH * DHEAD) + head * DHEAD) * NTOK;
        for (int o = t; o < DHEAD * NTOK; o += 256) {
            int d = o / NTOK, n = o % NTOK;
            float acc = 0.f;
#pragma unroll 7
            for (int m = 0; m < NTOK; m++) acc += y[(2 * KD + d) * NTOK + m] * att[n * NTOK + m];
            outw[d * NTOK + n] = acc;
            sp[o] = acc;
        }
        __syncthreads();
    }
}

// ---------------------------------------------------------------------------
// Window merge + residual
// ---------------------------------------------------------------------------
__global__ void __launch_bounds__(256) merge_res_kernel(
                                 const float* __restrict__ resid,
                                 const float* __restrict__ proj,
                                 float* __restrict__ out)
{
    size_t idx = (size_t)blockIdx.x * 256 + threadIdx.x;
    if (idx >= (size_t)TOT) return;
    int pos = (int)(idx % HW);
    int c = (int)((idx / HW) % ED);
    int b = (int)(idx / ((size_t)HW * ED));
    int h = pos / RES, x = pos % RES;
    int wy = h / WS, iy = h % WS, wx = x / WS, ix = x % WS;
    int win = (b * 4 + wy) * 4 + wx;
    out[idx] = resid[idx] + proj[((size_t)win * ED + c) * NTOK + iy * WS + ix];
}

// ---------------------------------------------------------------------------
extern "C" void kernel_launch(void* const* d_in, const int* in_sizes, int n_in,
                              void* d_out, int out_size)
{
    const float* x        = (const float*)d_in[0];
    const float* dw0_w    = (const float*)d_in[1];
    const float* dw0_b    = (const float*)d_in[2];
    const float* ffn0_w1  = (const float*)d_in[3];
    const float* ffn0_b1  = (const float*)d_in[4];
    const float* ffn0_w2  = (const float*)d_in[5];
    const float* ffn0_b2  = (const float*)d_in[6];
    const float* qkv_w    = (const float*)d_in[7];
    const float* qkv_b    = (const float*)d_in[8];
    const float* dwq_w7   = (const float*)d_in[9];
    const float* dwq_b7   = (const float*)d_in[10];
    const float* dwq_w5   = (const float*)d_in[11];
    const float* dwq_b5   = (const float*)d_in[12];
    const float* dwq_w3   = (const float*)d_in[13];
    const float* dwq_b3   = (const float*)d_in[14];
    const float* attn_bias= (const float*)d_in[15];
    const float* proj_w   = (const float*)d_in[16];
    const float* proj_b   = (const float*)d_in[17];
    const float* dw1_w    = (const float*)d_in[18];
    const float* dw1_b    = (const float*)d_in[19];
    const float* ffn1_w1  = (const float*)d_in[20];
    const float* ffn1_b1  = (const float*)d_in[21];
    const float* ffn1_w2  = (const float*)d_in[22];
    const float* ffn1_b2  = (const float*)d_in[23];

    float *pa, *pb, *pc, *ph;
    cudaGetSymbolAddress((void**)&pa, g_a);
    cudaGetSymbolAddress((void**)&pb, g_b);
    cudaGetSymbolAddress((void**)&pc, g_c);
    cudaGetSymbolAddress((void**)&ph, g_h);

    cudaFuncSetAttribute(attn_kernel, cudaFuncAttributeMaxDynamicSharedMemorySize, ATTN_SMEM_BYTES);

    dim3 dwgrid((HW + 255) / 256, BATCH * ED);

    // Stage 1: a = x + dwconv(x)
    dwconv_res_kernel<<<dwgrid, 256>>>(x, dw0_w, dw0_b, pa);
    // Stage 2: h = hswish(W1 a + b1); b = a + W2 h + b2
    gemm_tc_kernel<false, true, false><<<dim3(13, 8, BATCH), 256>>>(ffn0_w1, pa, ffn0_b1, nullptr, ph, 1024, HW, 512);
    gemm_tc_kernel<false, false, true><<<dim3(13, 4, BATCH), 256>>>(ffn0_w2, ph, ffn0_b2, pa, pb, 512, HW, 1024);
    // Stage 3: cascaded window attention -> c [1024,512,49]
    attn_kernel<<<NW_TOT, 256, ATTN_SMEM_BYTES>>>(pb, qkv_w, qkv_b, dwq_w7, dwq_b7, dwq_w5, dwq_b5,
                                                  dwq_w3, dwq_b3, attn_bias, pc);
    // Stage 4: proj on hswish(c) -> a [1024,512,49]
    gemm_tc_kernel<true, false, false><<<dim3(1, 4, NW_TOT), 256>>>(proj_w, pc, proj_b, nullptr, pa, 512, NTOK, 512);
    // Stage 5: c = b + merge(a)
    merge_res_kernel<<<(TOT + 255) / 256, 256>>>(pb, pa, pc);
    // Stage 6: b = c + dwconv(c)
    dwconv_res_kernel<<<dwgrid, 256>>>(pc, dw1_w, dw1_b, pb);
    // Stage 7: h = hswish(W1' b + b1'); out = b + W2' h + b2'
    gemm_tc_kernel<false, true, false><<<dim3(13, 8, BATCH), 256>>>(ffn1_w1, pb, ffn1_b1, nullptr, ph, 1024, HW, 512);
    gemm_tc_kernel<false, false, true><<<dim3(13, 4, BATCH), 256>>>(ffn1_w2, ph, ffn1_b2, pb, (float*)d_out, 512, HW, 1024);
}

// round 6
// speedup vs baseline: 2.3606x; 1.1165x over previous
#include <cuda_runtime.h>
#include <cuda_bf16.h>
#include <cstdint>
#include <cstring>
#include <math.h>

// Shapes
#define BATCH 64
#define ED 512
#define RES 28
#define HW 784
#define WS 7
#define NWIN 16
#define NW_TOT 1024
#define NH 8
#define KD 16
#define DHEAD 64
#define QKV_OUT 96
#define NTOK 49
#define NTOKP 56          // padded stride for attention output

#define TOT 25690112      // 64*512*784
#define HID_TOT 51380224  // 64*1024*784
#define CP_TOT (NW_TOT * ED * NTOKP)

// Scratch (device globals; no allocations allowed)
__device__ float    g_a[TOT];        // fp32 activations (dwconv out)
__device__ float    g_b[TOT];        // fp32 (ffn0 out / merge out, in-place)
__device__ float    g_d[TOT];        // fp32 proj out [win,512,49]
__device__ uint32_t g_ap[TOT];       // packed bf16 (hi,lo) of g_a
__device__ uint32_t g_hp[HID_TOT];   // packed mid activations
__device__ uint32_t g_cp[CP_TOT];    // packed attn out (hswish applied), stride 56
__device__ uint32_t g_w1p[1024 * 512];
__device__ uint32_t g_w2p[512 * 1024];
__device__ uint32_t g_w1bp[1024 * 512];
__device__ uint32_t g_w2bp[512 * 1024];
__device__ uint32_t g_projp[512 * 512];

__device__ __forceinline__ float hswish(float x) {
    return x * fminf(fmaxf(x + 3.f, 0.f), 6.f) * (1.f / 6.f);
}

// split fp32 -> (hi bf16 in low 16, lo bf16 in high 16)
__device__ __forceinline__ uint32_t pack_split(float v) {
    __nv_bfloat16 h = __float2bfloat16_rn(v);
    float hf = __bfloat162float(h);
    __nv_bfloat16 l = __float2bfloat16_rn(v - hf);
    unsigned short hu, lu;
    memcpy(&hu, &h, 2);
    memcpy(&lu, &l, 2);
    return (uint32_t)hu | ((uint32_t)lu << 16);
}

// ---------------------------------------------------------------------------
// Weight pre-split
// ---------------------------------------------------------------------------
__global__ void __launch_bounds__(256) pack_weights_kernel(
    const float* __restrict__ W, uint32_t* __restrict__ P, int n)
{
    int i = blockIdx.x * 256 + threadIdx.x;
    if (i < n) P[i] = pack_split(W[i]);
}

// ---------------------------------------------------------------------------
// Depthwise 3x3 conv + residual; optionally also emit packed bf16 planes
// ---------------------------------------------------------------------------
template<bool WBF>
__global__ void __launch_bounds__(256) dwconv_res_kernel(
    const float* __restrict__ x, const float* __restrict__ w,
    const float* __restrict__ bias, float* __restrict__ out,
    uint32_t* __restrict__ outp)
{
    int bc = blockIdx.y;
    int c = bc & (ED - 1);
    int pos = blockIdx.x * 256 + threadIdx.x;
    if (pos >= HW) return;
    int h = pos / RES, ww = pos % RES;
    const float* xp = x + (size_t)bc * HW;
    const float* wp = w + c * 9;
    float acc = bias[c];
#pragma unroll
    for (int dy = 0; dy < 3; dy++) {
        int yy = h + dy - 1;
        if (yy < 0 || yy >= RES) continue;
#pragma unroll
        for (int dx = 0; dx < 3; dx++) {
            int xx = ww + dx - 1;
            if (xx < 0 || xx >= RES) continue;
            acc += xp[yy * RES + xx] * wp[dy * 3 + dx];
        }
    }
    float r = xp[pos] + acc;
    out[(size_t)bc * HW + pos] = r;
    if (WBF) outp[(size_t)bc * HW + pos] = pack_split(r);
}

// ---------------------------------------------------------------------------
// Tensor-core GEMM on pre-split packed bf16 inputs.
//   Ap: [M,K] packed weights; Bp: [Z][K][NSB] packed activations
//   OUT_BF: write hswish(v) packed to Cp [Z][M][NSC]; else fp32 (+resid) to Cf
// CTA tile 128x64, K-chunk 32, 8 warps (4m x 2n), warp tile 32x32, ldmatrix.
// ---------------------------------------------------------------------------
#define KCP 40

__device__ __forceinline__ void mma_bf16(float* c, uint32_t a0, uint32_t a1,
                                         uint32_t a2, uint32_t a3,
                                         uint32_t b0, uint32_t b1)
{
    asm volatile(
        "mma.sync.aligned.m16n8k16.row.col.f32.bf16.bf16.f32 "
        "{%0,%1,%2,%3}, {%4,%5,%6,%7}, {%8,%9}, {%0,%1,%2,%3};\n"
        : "+f"(c[0]), "+f"(c[1]), "+f"(c[2]), "+f"(c[3])
        : "r"(a0), "r"(a1), "r"(a2), "r"(a3), "r"(b0), "r"(b1));
}

__device__ __forceinline__ void ldsm4(uint32_t& r0, uint32_t& r1,
                                      uint32_t& r2, uint32_t& r3, uint32_t addr)
{
    asm volatile("ldmatrix.sync.aligned.m8n8.x4.shared.b16 {%0,%1,%2,%3}, [%4];"
                 : "=r"(r0), "=r"(r1), "=r"(r2), "=r"(r3) : "r"(addr));
}

template<bool OUT_BF, bool RESID>
__global__ void __launch_bounds__(256) gemm_bf_kernel(
    const uint32_t* __restrict__ Ap,
    const uint32_t* __restrict__ Bp,
    const float* __restrict__ bias,
    const float* __restrict__ resid,
    float* __restrict__ Cf,
    uint32_t* __restrict__ Cp,
    int M, int N, int NSB, int NSC, int K)
{
    __shared__ unsigned short AhS[128 * KCP];
    __shared__ unsigned short AlS[128 * KCP];
    __shared__ unsigned short BhS[64 * KCP];
    __shared__ unsigned short BlS[64 * KCP];

    int z = blockIdx.z;
    int m0 = blockIdx.y * 128;
    int n0 = blockIdx.x * 64;
    const uint32_t* Bz = Bp + (size_t)z * K * NSB;
    bool fulln = (n0 + 64 <= N);

    int t = threadIdx.x;
    int warp = t >> 5, lane = t & 31;
    int wm = warp & 3, wn = warp >> 2;
    int m0w = wm * 32, n0w = wn * 32;
    int g = lane >> 2, tig = lane & 3;
    int lane7 = lane & 7, l8 = (lane >> 3) & 1, l16 = lane >> 4;

    uint32_t sAh = (uint32_t)__cvta_generic_to_shared(AhS);
    uint32_t sAl = (uint32_t)__cvta_generic_to_shared(AlS);
    uint32_t sBh = (uint32_t)__cvta_generic_to_shared(BhS);
    uint32_t sBl = (uint32_t)__cvta_generic_to_shared(BlS);

    float acc[2][4][4];
#pragma unroll
    for (int i = 0; i < 2; i++)
#pragma unroll
        for (int j = 0; j < 4; j++)
#pragma unroll
            for (int q = 0; q < 4; q++) acc[i][j][q] = 0.f;

    for (int k0 = 0; k0 < K; k0 += 32) {
        // Stage A: 128x32 packed -> hi/lo planes (vectorized)
#pragma unroll
        for (int it = 0; it < 4; it++) {
            int gg = t + it * 256;
            int m = gg >> 3, kq = (gg & 7) * 4;
            uint4 v = *(const uint4*)&Ap[(size_t)(m0 + m) * K + k0 + kq];
            uint32_t h01 = (v.x & 0xffffu) | (v.y << 16);
            uint32_t h23 = (v.z & 0xffffu) | (v.w << 16);
            uint32_t l01 = (v.x >> 16) | (v.y & 0xffff0000u);
            uint32_t l23 = (v.z >> 16) | (v.w & 0xffff0000u);
            *(uint2*)&AhS[m * KCP + kq] = make_uint2(h01, h23);
            *(uint2*)&AlS[m * KCP + kq] = make_uint2(l01, l23);
        }
        // Stage B: 32x64 packed, transposed into [n][k] planes
#pragma unroll
        for (int it = 0; it < 4; it++) {
            int gg = t + it * 256;
            int kb = gg >> 5, n2 = (gg & 31) * 2;
            uint32_t p0 = 0, p1 = 0;
            if (fulln) {
                uint2 v = *(const uint2*)&Bz[(size_t)(k0 + kb) * NSB + n0 + n2];
                p0 = v.x; p1 = v.y;
            } else {
                if (n0 + n2 < N)     p0 = Bz[(size_t)(k0 + kb) * NSB + n0 + n2];
                if (n0 + n2 + 1 < N) p1 = Bz[(size_t)(k0 + kb) * NSB + n0 + n2 + 1];
            }
            BhS[n2 * KCP + kb]       = (unsigned short)(p0 & 0xffffu);
            BlS[n2 * KCP + kb]       = (unsigned short)(p0 >> 16);
            BhS[(n2 + 1) * KCP + kb] = (unsigned short)(p1 & 0xffffu);
            BlS[(n2 + 1) * KCP + kb] = (unsigned short)(p1 >> 16);
        }
        __syncthreads();

#pragma unroll
        for (int kk = 0; kk < 32; kk += 16) {
            uint32_t ah[2][4], al[2][4], bh[4][2], bl[4][2];
#pragma unroll
            for (int i = 0; i < 2; i++) {
                int row = m0w + i * 16 + lane7 + l8 * 8;
                uint32_t off = (uint32_t)(row * KCP + kk + l16 * 8) * 2;
                ldsm4(ah[i][0], ah[i][1], ah[i][2], ah[i][3], sAh + off);
                ldsm4(al[i][0], al[i][1], al[i][2], al[i][3], sAl + off);
            }
#pragma unroll
            for (int jp = 0; jp < 2; jp++) {
                int row = n0w + jp * 16 + l16 * 8 + lane7;
                uint32_t off = (uint32_t)(row * KCP + kk + l8 * 8) * 2;
                ldsm4(bh[2 * jp][0], bh[2 * jp][1], bh[2 * jp + 1][0], bh[2 * jp + 1][1], sBh + off);
                ldsm4(bl[2 * jp][0], bl[2 * jp][1], bl[2 * jp + 1][0], bl[2 * jp + 1][1], sBl + off);
            }
#pragma unroll
            for (int i = 0; i < 2; i++)
#pragma unroll
                for (int j = 0; j < 4; j++) {
                    mma_bf16(acc[i][j], ah[i][0], ah[i][1], ah[i][2], ah[i][3],
                             bh[j][0], bh[j][1]);
                    mma_bf16(acc[i][j], ah[i][0], ah[i][1], ah[i][2], ah[i][3],
                             bl[j][0], bl[j][1]);
                    mma_bf16(acc[i][j], al[i][0], al[i][1], al[i][2], al[i][3],
                             bh[j][0], bh[j][1]);
                }
        }
        __syncthreads();
    }

    // Epilogue
#pragma unroll
    for (int i = 0; i < 2; i++) {
#pragma unroll
        for (int j = 0; j < 4; j++) {
            int r0 = m0 + m0w + i * 16 + g;
            int r1 = r0 + 8;
            int cb = n0 + n0w + j * 8 + tig * 2;
            float b0v = bias[r0], b1v = bias[r1];
#pragma unroll
            for (int q = 0; q < 2; q++) {
                int n = cb + q;
                if (n < N) {
                    float v0 = acc[i][j][q] + b0v;
                    float v1 = acc[i][j][q + 2] + b1v;
                    if (OUT_BF) {
                        Cp[(size_t)z * M * NSC + (size_t)r0 * NSC + n] = pack_split(hswish(v0));
                        Cp[(size_t)z * M * NSC + (size_t)r1 * NSC + n] = pack_split(hswish(v1));
                    } else {
                        size_t o0 = (size_t)z * M * NSC + (size_t)r0 * NSC + n;
                        size_t o1 = (size_t)z * M * NSC + (size_t)r1 * NSC + n;
                        if (RESID) { v0 += resid[o0]; v1 += resid[o1]; }
                        Cf[o0] = v0;
                        Cf[o1] = v1;
                    }
                }
            }
        }
    }
}

// ---------------------------------------------------------------------------
// Cascaded window attention; output = packed bf16 of hswish(head outputs)
// ---------------------------------------------------------------------------
#define ATTN_SMEM_FLOATS (64*49 + 96*49 + 16*49 + 49*49 + 96*64 + 96 + 49)
#define ATTN_SMEM_BYTES  (ATTN_SMEM_FLOATS * 4)

__global__ void __launch_bounds__(256) attn_kernel(
    const float* __restrict__ xin,
    const float* __restrict__ qkv_w,
    const float* __restrict__ qkv_b,
    const float* __restrict__ w7, const float* __restrict__ b7,
    const float* __restrict__ w5, const float* __restrict__ b5,
    const float* __restrict__ w3, const float* __restrict__ b3,
    const float* __restrict__ attn_bias,
    uint32_t* __restrict__ out)   // [1024,512,NTOKP] packed
{
    extern __shared__ float smem[];
    float* sp  = smem;
    float* y   = sp  + 64 * 49;
    float* qc  = y   + 96 * 49;
    float* att = qc  + 16 * 49;
    float* wsm = att + 49 * 49;
    float* bsm = wsm + 96 * 64;
    float* bia = bsm + 96;

    int w = blockIdx.x;
    int b = w >> 4, wy = (w >> 2) & 3, wx = w & 3;
    int t = threadIdx.x;
    const float* xb = xin + (size_t)b * ED * HW;

    for (int head = 0; head < NH; head++) {
        for (int i = t; i < QKV_OUT * DHEAD; i += 256) wsm[i] = qkv_w[head * QKV_OUT * DHEAD + i];
        if (t < QKV_OUT) bsm[t] = qkv_b[head * QKV_OUT + t];
        if (t < NTOK)    bia[t] = attn_bias[head * NTOK + t];
        for (int i = t; i < DHEAD * NTOK; i += 256) {
            int c = i / NTOK, n = i % NTOK;
            int iy = n / WS, ix = n % WS;
            float xv = xb[(size_t)(head * DHEAD + c) * HW + (wy * WS + iy) * RES + (wx * WS + ix)];
            sp[i] = (head == 0) ? xv : sp[i] + xv;
        }
        __syncthreads();
        for (int o = t; o < QKV_OUT * NTOK; o += 256) {
            int m = o / NTOK, n = o % NTOK;
            float acc = bsm[m];
            const float* wr = &wsm[m * DHEAD];
#pragma unroll 8
            for (int c = 0; c < DHEAD; c++) acc += wr[c] * sp[c * NTOK + n];
            y[o] = acc;
        }
        __syncthreads();
        int ksz; const float* dw; const float* db;
        if (head == 0)      { ksz = 7; dw = w7; db = b7; }
        else if (head == 1) { ksz = 5; dw = w5; db = b5; }
        else                { ksz = 3; dw = w3 + (head - 2) * KD * 9; db = b3 + (head - 2) * KD; }
        int pad = ksz >> 1;
        for (int o = t; o < KD * NTOK; o += 256) {
            int c = o / NTOK, n = o % NTOK;
            int iy = n / WS, ix = n % WS;
            float acc = db[c];
            for (int dy = 0; dy < ksz; dy++) {
                int yy = iy + dy - pad;
                if (yy < 0 || yy >= WS) continue;
                for (int dx = 0; dx < ksz; dx++) {
                    int xx = ix + dx - pad;
                    if (xx < 0 || xx >= WS) continue;
                    acc += y[c * NTOK + yy * WS + xx] * dw[c * ksz * ksz + dy * ksz + dx];
                }
            }
            qc[o] = acc;
        }
        __syncthreads();
        for (int o = t; o < NTOK * NTOK; o += 256) {
            int n = o / NTOK, m = o % NTOK;
            float acc = 0.f;
#pragma unroll
            for (int c = 0; c < KD; c++) acc += qc[c * NTOK + n] * y[(KD + c) * NTOK + m];
            int ny = n / WS, nx = n % WS, my = m / WS, mx = m % WS;
            att[o] = acc * 0.25f + bia[abs(ny - my) * WS + abs(nx - mx)];
        }
        __syncthreads();
        if (t < NTOK) {
            float mx = -1e30f;
            for (int m = 0; m < NTOK; m++) mx = fmaxf(mx, att[t * NTOK + m]);
            float s = 0.f;
            for (int m = 0; m < NTOK; m++) { float e = expf(att[t * NTOK + m] - mx); att[t * NTOK + m] = e; s += e; }
            float inv = 1.f / s;
            for (int m = 0; m < NTOK; m++) att[t * NTOK + m] *= inv;
        }
        __syncthreads();
        uint32_t* outw = out + ((size_t)w * ED + head * DHEAD) * NTOKP;
        for (int o = t; o < DHEAD * NTOK; o += 256) {
            int d = o / NTOK, n = o % NTOK;
            float acc = 0.f;
#pragma unroll 7
            for (int m = 0; m < NTOK; m++) acc += y[(2 * KD + d) * NTOK + m] * att[n * NTOK + m];
            outw[d * NTOKP + n] = pack_split(hswish(acc));
            sp[o] = acc;
        }
        __syncthreads();
    }
}

// ---------------------------------------------------------------------------
// Window merge + residual (in-place on resid buffer is safe: elementwise)
// ---------------------------------------------------------------------------
__global__ void __launch_bounds__(256) merge_res_kernel(
    const float* __restrict__ resid,
    const float* __restrict__ proj,
    float* __restrict__ out)
{
    size_t idx = (size_t)blockIdx.x * 256 + threadIdx.x;
    if (idx >= (size_t)TOT) return;
    int pos = (int)(idx % HW);
    int c = (int)((idx / HW) % ED);
    int b = (int)(idx / ((size_t)HW * ED));
    int h = pos / RES, x = pos % RES;
    int wy = h / WS, iy = h % WS, wx = x / WS, ix = x % WS;
    int win = (b * 4 + wy) * 4 + wx;
    out[idx] = resid[idx] + proj[((size_t)win * ED + c) * NTOK + iy * WS + ix];
}

// ---------------------------------------------------------------------------
extern "C" void kernel_launch(void* const* d_in, const int* in_sizes, int n_in,
                              void* d_out, int out_size)
{
    const float* x        = (const float*)d_in[0];
    const float* dw0_w    = (const float*)d_in[1];
    const float* dw0_b    = (const float*)d_in[2];
    const float* ffn0_w1  = (const float*)d_in[3];
    const float* ffn0_b1  = (const float*)d_in[4];
    const float* ffn0_w2  = (const float*)d_in[5];
    const float* ffn0_b2  = (const float*)d_in[6];
    const float* qkv_w    = (const float*)d_in[7];
    const float* qkv_b    = (const float*)d_in[8];
    const float* dwq_w7   = (const float*)d_in[9];
    const float* dwq_b7   = (const float*)d_in[10];
    const float* dwq_w5   = (const float*)d_in[11];
    const float* dwq_b5   = (const float*)d_in[12];
    const float* dwq_w3   = (const float*)d_in[13];
    const float* dwq_b3   = (const float*)d_in[14];
    const float* attn_bias= (const float*)d_in[15];
    const float* proj_w   = (const float*)d_in[16];
    const float* proj_b   = (const float*)d_in[17];
    const float* dw1_w    = (const float*)d_in[18];
    const float* dw1_b    = (const float*)d_in[19];
    const float* ffn1_w1  = (const float*)d_in[20];
    const float* ffn1_b1  = (const float*)d_in[21];
    const float* ffn1_w2  = (const float*)d_in[22];
    const float* ffn1_b2  = (const float*)d_in[23];

    float *pa, *pb, *pd;
    uint32_t *pap, *php, *pcp, *pw1, *pw2, *pw1b, *pw2b, *pproj;
    cudaGetSymbolAddress((void**)&pa, g_a);
    cudaGetSymbolAddress((void**)&pb, g_b);
    cudaGetSymbolAddress((void**)&pd, g_d);
    cudaGetSymbolAddress((void**)&pap, g_ap);
    cudaGetSymbolAddress((void**)&php, g_hp);
    cudaGetSymbolAddress((void**)&pcp, g_cp);
    cudaGetSymbolAddress((void**)&pw1, g_w1p);
    cudaGetSymbolAddress((void**)&pw2, g_w2p);
    cudaGetSymbolAddress((void**)&pw1b, g_w1bp);
    cudaGetSymbolAddress((void**)&pw2b, g_w2bp);
    cudaGetSymbolAddress((void**)&pproj, g_projp);

    cudaFuncSetAttribute(attn_kernel, cudaFuncAttributeMaxDynamicSharedMemorySize, ATTN_SMEM_BYTES);

    // Weight pre-split (cheap; graph-capturable kernel launches)
    pack_weights_kernel<<<2048, 256>>>(ffn0_w1, pw1, 1024 * 512);
    pack_weights_kernel<<<2048, 256>>>(ffn0_w2, pw2, 512 * 1024);
    pack_weights_kernel<<<2048, 256>>>(ffn1_w1, pw1b, 1024 * 512);
    pack_weights_kernel<<<2048, 256>>>(ffn1_w2, pw2b, 512 * 1024);
    pack_weights_kernel<<<1024, 256>>>(proj_w, pproj, 512 * 512);

    dim3 dwgrid((HW + 255) / 256, BATCH * ED);

    // Stage 1: a = x + dwconv(x)  (fp32 + packed)
    dwconv_res_kernel<true><<<dwgrid, 256>>>(x, dw0_w, dw0_b, pa, pap);
    // Stage 2: hp = split(hswish(W1 a + b1)); b = a + W2 h + b2
    gemm_bf_kernel<true, false><<<dim3(13, 8, BATCH), 256>>>(pw1, pap, ffn0_b1, nullptr,
        nullptr, php, 1024, HW, HW, HW, 512);
    gemm_bf_kernel<false, true><<<dim3(13, 4, BATCH), 256>>>(pw2, php, ffn0_b2, pa,
        pb, nullptr, 512, HW, HW, HW, 1024);
    // Stage 3: attention -> cp packed (hswish applied), stride 56
    attn_kernel<<<NW_TOT, 256, ATTN_SMEM_BYTES>>>(pb, qkv_w, qkv_b, dwq_w7, dwq_b7,
        dwq_w5, dwq_b5, dwq_w3, dwq_b3, attn_bias, pcp);
    // Stage 4: proj -> d fp32 [win,512,49]
    gemm_bf_kernel<false, false><<<dim3(1, 4, NW_TOT), 256>>>(pproj, pcp, proj_b, nullptr,
        pd, nullptr, 512, NTOK, NTOKP, NTOK, 512);
    // Stage 5: b = b + merge(d)   (in-place)
    merge_res_kernel<<<(TOT + 255) / 256, 256>>>(pb, pd, pb);
    // Stage 6: a = b + dwconv(b)  (fp32 + packed)
    dwconv_res_kernel<true><<<dwgrid, 256>>>(pb, dw1_w, dw1_b, pa, pap);
    // Stage 7: hp = split(hswish(W1' a + b1')); out = a + W2' h + b2'
    gemm_bf_kernel<true, false><<<dim3(13, 8, BATCH), 256>>>(pw1b, pap, ffn1_b1, nullptr,
        nullptr, php, 1024, HW, HW, HW, 512);
    gemm_bf_kernel<false, true><<<dim3(13, 4, BATCH), 256>>>(pw2b, php, ffn1_b2, pa,
        (float*)d_out, nullptr, 512, HW, HW, HW, 1024);
}

// round 8
// speedup vs baseline: 4.0878x; 1.7317x over previous
#include <cuda_runtime.h>
#include <cuda_bf16.h>
#include <cstdint>
#include <cstring>
#include <math.h>

typedef unsigned short ushort_t;

// Shapes
#define BATCH 64
#define ED 512
#define RES 28
#define HW 784
#define WS 7
#define NW_TOT 1024
#define NH 8
#define KD 16
#define DHEAD 64
#define QKV_OUT 96
#define NTOK 49
#define NTOKP 56

#define NTOT 50176        // 64*784
#define NPROJ 57344       // 1024*56

// Scratch (device globals)
__device__ float    g_af[ED * NTOT];        // dwconv out fp32 c-major (resid)
__device__ float    g_bf[ED * NTOT];        // ffn0 out / merged fp32 c-major
__device__ ushort_t g_ah[ED * NTOT];        // hi plane of dwconv out
__device__ ushort_t g_al[ED * NTOT];        // lo plane
__device__ ushort_t g_hh[2 * ED * NTOT];    // hidden hi [1024][NTOT]
__device__ ushort_t g_hl[2 * ED * NTOT];
__device__ ushort_t g_ch[ED * NPROJ];       // attn out hi [512][NPROJ]
__device__ ushort_t g_cl[ED * NPROJ];
__device__ ushort_t g_w1h[1024 * 512], g_w1l[1024 * 512];
__device__ ushort_t g_w2h[512 * 1024], g_w2l[512 * 1024];
__device__ ushort_t g_w1bh[1024 * 512], g_w1bl[1024 * 512];
__device__ ushort_t g_w2bh[512 * 1024], g_w2bl[512 * 1024];
__device__ ushort_t g_pjh[512 * 512], g_pjl[512 * 512];

__device__ __forceinline__ float hswish(float x) {
    return x * fminf(fmaxf(x + 3.f, 0.f), 6.f) * (1.f / 6.f);
}
__device__ __forceinline__ void split2(float v, ushort_t& h, ushort_t& l) {
    __nv_bfloat16 hb = __float2bfloat16_rn(v);
    float hf = __bfloat162float(hb);
    __nv_bfloat16 lb = __float2bfloat16_rn(v - hf);
    memcpy(&h, &hb, 2);
    memcpy(&l, &lb, 2);
}
__device__ __forceinline__ uint32_t smem_u32(const void* p) {
    return (uint32_t)__cvta_generic_to_shared(p);
}
__device__ __forceinline__ void cpasync16(uint32_t dst, const void* src) {
    asm volatile("cp.async.cg.shared.global [%0], [%1], 16;" :: "r"(dst), "l"(src));
}
__device__ __forceinline__ void mma_bf16(float* c, const uint32_t* a, const uint32_t* b)
{
    asm volatile(
        "mma.sync.aligned.m16n8k16.row.col.f32.bf16.bf16.f32 "
        "{%0,%1,%2,%3}, {%4,%5,%6,%7}, {%8,%9}, {%0,%1,%2,%3};\n"
        : "+f"(c[0]), "+f"(c[1]), "+f"(c[2]), "+f"(c[3])
        : "r"(a[0]), "r"(a[1]), "r"(a[2]), "r"(a[3]), "r"(b[0]), "r"(b[1]));
}
__device__ __forceinline__ void ldsm4(uint32_t& r0, uint32_t& r1,
                                      uint32_t& r2, uint32_t& r3, uint32_t addr)
{
    asm volatile("ldmatrix.sync.aligned.m8n8.x4.shared.b16 {%0,%1,%2,%3}, [%4];"
                 : "=r"(r0), "=r"(r1), "=r"(r2), "=r"(r3) : "r"(addr));
}
__device__ __forceinline__ void ldsm4t(uint32_t& r0, uint32_t& r1,
                                       uint32_t& r2, uint32_t& r3, uint32_t addr)
{
    asm volatile("ldmatrix.sync.aligned.m8n8.x4.trans.shared.b16 {%0,%1,%2,%3}, [%4];"
                 : "=r"(r0), "=r"(r1), "=r"(r2), "=r"(r3) : "r"(addr));
}

// ---------------------------------------------------------------------------
// Weight pre-split into hi/lo planes
// ---------------------------------------------------------------------------
__global__ void __launch_bounds__(256) pack_weights_kernel(
    const float* __restrict__ W, ushort_t* __restrict__ Ph,
    ushort_t* __restrict__ Pl, int n)
{
    int i = blockIdx.x * 256 + threadIdx.x;
    if (i < n) {
        ushort_t h, l;
        split2(W[i], h, l);
        Ph[i] = h; Pl[i] = l;
    }
}

// ---------------------------------------------------------------------------
// Depthwise 3x3 conv + residual. IN_CM: input c-major; else [b][c][hw].
// Writes fp32 c-major + hi/lo planes.
// ---------------------------------------------------------------------------
template<bool IN_CM>
__global__ void __launch_bounds__(256) dwconv_res_kernel(
    const float* __restrict__ x, const float* __restrict__ w,
    const float* __restrict__ bias, float* __restrict__ out,
    ushort_t* __restrict__ oh, ushort_t* __restrict__ ol)
{
    int bc = blockIdx.y;
    int c = bc & (ED - 1);
    int b = bc >> 9;
    int pos = blockIdx.x * 256 + threadIdx.x;
    if (pos >= HW) return;
    int h = pos / RES, ww = pos % RES;
    const float* xp = IN_CM ? (x + (size_t)c * NTOT + (size_t)b * HW)
                            : (x + (size_t)bc * HW);
    const float* wp = w + c * 9;
    float acc = bias[c];
#pragma unroll
    for (int dy = 0; dy < 3; dy++) {
        int yy = h + dy - 1;
        if (yy < 0 || yy >= RES) continue;
#pragma unroll
        for (int dx = 0; dx < 3; dx++) {
            int xx = ww + dx - 1;
            if (xx < 0 || xx >= RES) continue;
            acc += xp[yy * RES + xx] * wp[dy * 3 + dx];
        }
    }
    float r = xp[pos] + acc;
    size_t o = (size_t)c * NTOT + (size_t)b * HW + pos;
    out[o] = r;
    ushort_t hh, ll;
    split2(r, hh, ll);
    oh[o] = hh; ol[o] = ll;
}

// ---------------------------------------------------------------------------
// HMMA GEMM with cp.async double-buffered hi/lo planes.
//   A: [M][K] weight planes; B: [K][NB] activation planes. CTA 128x64, chunk 32.
// MODE 0: hidden: planes = split(hswish(v+bias))
// MODE 1: Cf = v+bias+resid (c-major)
// MODE 2: proj+merge: Cf[spatial] += v+bias (tok<49 only)
// MODE 3: final: out[b][m][pos] = v+bias+resid
// smem per stage: Ah 8K | Al 8K | Bh 4K | Bl 4K  = 24576; 2 stages = 49152
// ---------------------------------------------------------------------------
template<int MODE>
__global__ void __launch_bounds__(256) gemm_cp_kernel(
    const ushort_t* __restrict__ Awh, const ushort_t* __restrict__ Awl,
    const ushort_t* __restrict__ Bh,  const ushort_t* __restrict__ Bl,
    const float* __restrict__ bias, const float* __restrict__ resid,
    float* __restrict__ Cf, ushort_t* __restrict__ Chh, ushort_t* __restrict__ Chl,
    int M, int NB, int K)
{
    extern __shared__ char sm[];
    int t = threadIdx.x;
    int warp = t >> 5, lane = t & 31;
    int wm = warp & 3, wn = warp >> 2;
    int m0w = wm * 32, n0w = wn * 32;
    int g = lane >> 2, tig = lane & 3;
    int m0 = blockIdx.y * 128, n0 = blockIdx.x * 64;
    uint32_t sbase = smem_u32(sm);

    float acc[2][4][4];
#pragma unroll
    for (int i = 0; i < 2; i++)
#pragma unroll
        for (int j = 0; j < 4; j++)
#pragma unroll
            for (int q = 0; q < 4; q++) acc[i][j][q] = 0.f;

    auto stage = [&](int k0, int buf) {
        uint32_t soff = sbase + buf * 24576;
#pragma unroll
        for (int i = 0; i < 2; i++) {
            int idx = t + i * 256;
            int m = idx >> 2, c = idx & 3;
            uint32_t d = soff + m * 64 + ((c ^ ((m >> 1) & 3)) << 4);
            const ushort_t* sh = Awh + (size_t)(m0 + m) * K + k0 + c * 8;
            const ushort_t* sl = Awl + (size_t)(m0 + m) * K + k0 + c * 8;
            cpasync16(d, sh);
            cpasync16(d + 8192, sl);
        }
        {
            int k = t >> 3, c = t & 7;
            uint32_t d = soff + 16384 + k * 128 + ((c ^ (k & 7)) << 4);
            const ushort_t* sh = Bh + (size_t)(k0 + k) * NB + n0 + c * 8;
            const ushort_t* sl = Bl + (size_t)(k0 + k) * NB + n0 + c * 8;
            cpasync16(d, sh);
            cpasync16(d + 4096, sl);
        }
        asm volatile("cp.async.commit_group;" ::: "memory");
    };

    stage(0, 0);
    int nk = K >> 5;
    for (int kc = 0; kc < nk; kc++) {
        if (kc + 1 < nk) {
            stage((kc + 1) << 5, (kc + 1) & 1);
            asm volatile("cp.async.wait_group 1;" ::: "memory");
        } else {
            asm volatile("cp.async.wait_group 0;" ::: "memory");
        }
        __syncthreads();
        uint32_t soff = sbase + (kc & 1) * 24576;
#pragma unroll
        for (int kk = 0; kk < 32; kk += 16) {
            uint32_t ah[2][4], al[2][4], bh[4][2], bl[4][2];
#pragma unroll
            for (int i = 0; i < 2; i++) {
                int row = m0w + i * 16 + (lane & 15);
                int c = (kk >> 3) + (lane >> 4);
                uint32_t a = soff + row * 64 + ((c ^ ((row >> 1) & 3)) << 4);
                ldsm4(ah[i][0], ah[i][1], ah[i][2], ah[i][3], a);
                ldsm4(al[i][0], al[i][1], al[i][2], al[i][3], a + 8192);
            }
#pragma unroll
            for (int j = 0; j < 2; j++) {
                int krow = kk + (lane & 15);
                int cn = wn * 4 + j * 2 + (lane >> 4);
                uint32_t a = soff + 16384 + krow * 128 + ((cn ^ (krow & 7)) << 4);
                ldsm4t(bh[j*2][0], bh[j*2][1], bh[j*2+1][0], bh[j*2+1][1], a);
                ldsm4t(bl[j*2][0], bl[j*2][1], bl[j*2+1][0], bl[j*2+1][1], a + 4096);
            }
#pragma unroll
            for (int i = 0; i < 2; i++)
#pragma unroll
                for (int j = 0; j < 4; j++) {
                    mma_bf16(acc[i][j], ah[i], bh[j]);
                    mma_bf16(acc[i][j], ah[i], bl[j]);
                    mma_bf16(acc[i][j], al[i], bh[j]);
                }
        }
        __syncthreads();
    }

    // Epilogue
#pragma unroll
    for (int i = 0; i < 2; i++) {
        int r0 = m0 + m0w + i * 16 + g;
        int r1 = r0 + 8;
        float b0v = bias[r0], b1v = bias[r1];
#pragma unroll
        for (int j = 0; j < 4; j++) {
            int cb = n0 + n0w + j * 8 + tig * 2;
            float v00 = acc[i][j][0] + b0v, v01 = acc[i][j][1] + b0v;
            float v10 = acc[i][j][2] + b1v, v11 = acc[i][j][3] + b1v;
            if (MODE == 0) {
                ushort_t h0, l0, h1, l1;
                split2(hswish(v00), h0, l0);
                split2(hswish(v01), h1, l1);
                *(uint32_t*)&Chh[(size_t)r0 * NB + cb] = (uint32_t)h0 | ((uint32_t)h1 << 16);
                *(uint32_t*)&Chl[(size_t)r0 * NB + cb] = (uint32_t)l0 | ((uint32_t)l1 << 16);
                split2(hswish(v10), h0, l0);
                split2(hswish(v11), h1, l1);
                *(uint32_t*)&Chh[(size_t)r1 * NB + cb] = (uint32_t)h0 | ((uint32_t)h1 << 16);
                *(uint32_t*)&Chl[(size_t)r1 * NB + cb] = (uint32_t)l0 | ((uint32_t)l1 << 16);
            } else if (MODE == 1) {
                size_t o0 = (size_t)r0 * NB + cb;
                size_t o1 = (size_t)r1 * NB + cb;
                float2 rr0 = *(const float2*)&resid[o0];
                float2 rr1 = *(const float2*)&resid[o1];
                *(float2*)&Cf[o0] = make_float2(v00 + rr0.x, v01 + rr0.y);
                *(float2*)&Cf[o1] = make_float2(v10 + rr1.x, v11 + rr1.y);
            } else if (MODE == 2) {
                float vs[4] = {v00, v01, v10, v11};
#pragma unroll
                for (int q = 0; q < 4; q++) {
                    int col = cb + (q & 1);
                    int r = (q < 2) ? r0 : r1;
                    int win = col / NTOKP, tok = col % NTOKP;
                    if (tok < NTOK) {
                        int b = win >> 4, wy = (win >> 2) & 3, wx = win & 3;
                        int iy = tok / WS, ix = tok % WS;
                        size_t o = (size_t)r * NTOT + (size_t)b * HW
                                 + (wy * WS + iy) * RES + (wx * WS + ix);
                        Cf[o] = Cf[o] + vs[q];
                    }
                }
            } else {
                int b = cb / HW, pos = cb % HW;
                size_t o0 = (size_t)r0 * NB + cb;
                size_t o1 = (size_t)r1 * NB + cb;
                float2 rr0 = *(const float2*)&resid[o0];
                float2 rr1 = *(const float2*)&resid[o1];
                *(float2*)&Cf[((size_t)b * ED + r0) * HW + pos] =
                    make_float2(v00 + rr0.x, v01 + rr0.y);
                *(float2*)&Cf[((size_t)b * ED + r1) * HW + pos] =
                    make_float2(v10 + rr1.x, v11 + rr1.y);
            }
        }
    }
}

// ---------------------------------------------------------------------------
// Cascaded window attention; c-major fp32 input; hi/lo plane output [512][NPROJ]
// ---------------------------------------------------------------------------
#define ATTN_SMEM_FLOATS (64*49 + 96*49 + 16*49 + 49*49 + 96*64 + 96 + 49)
#define ATTN_SMEM_BYTES  (ATTN_SMEM_FLOATS * 4)

__global__ void __launch_bounds__(256) attn_kernel(
    const float* __restrict__ xin,
    const float* __restrict__ qkv_w,
    const float* __restrict__ qkv_b,
    const float* __restrict__ w7, const float* __restrict__ b7,
    const float* __restrict__ w5, const float* __restrict__ b5,
    const float* __restrict__ w3, const float* __restrict__ b3,
    const float* __restrict__ attn_bias,
    ushort_t* __restrict__ oh, ushort_t* __restrict__ ol)
{
    extern __shared__ float smem[];
    float* sp  = smem;
    float* y   = sp  + 64 * 49;
    float* qc  = y   + 96 * 49;
    float* att = qc  + 16 * 49;
    float* wsm = att + 49 * 49;
    float* bsm = wsm + 96 * 64;
    float* bia = bsm + 96;

    int w = blockIdx.x;
    int b = w >> 4, wy = (w >> 2) & 3, wx = w & 3;
    int t = threadIdx.x;

    for (int head = 0; head < NH; head++) {
        for (int i = t; i < QKV_OUT * DHEAD; i += 256) wsm[i] = qkv_w[head * QKV_OUT * DHEAD + i];
        if (t < QKV_OUT) bsm[t] = qkv_b[head * QKV_OUT + t];
        if (t < NTOK)    bia[t] = attn_bias[head * NTOK + t];
        for (int i = t; i < DHEAD * NTOK; i += 256) {
            int c = i / NTOK, n = i % NTOK;
            int iy = n / WS, ix = n % WS;
            float xv = xin[(size_t)(head * DHEAD + c) * NTOT + (size_t)b * HW
                           + (wy * WS + iy) * RES + (wx * WS + ix)];
            sp[i] = (head == 0) ? xv : sp[i] + xv;
        }
        __syncthreads();
        for (int o = t; o < QKV_OUT * NTOK; o += 256) {
            int m = o / NTOK, n = o % NTOK;
            float acc = bsm[m];
            const float* wr = &wsm[m * DHEAD];
#pragma unroll 8
            for (int c = 0; c < DHEAD; c++) acc += wr[c] * sp[c * NTOK + n];
            y[o] = acc;
        }
        __syncthreads();
        int ksz; const float* dw; const float* db;
        if (head == 0)      { ksz = 7; dw = w7; db = b7; }
        else if (head == 1) { ksz = 5; dw = w5; db = b5; }
        else                { ksz = 3; dw = w3 + (head - 2) * KD * 9; db = b3 + (head - 2) * KD; }
        int pad = ksz >> 1;
        for (int o = t; o < KD * NTOK; o += 256) {
            int c = o / NTOK, n = o % NTOK;
            int iy = n / WS, ix = n % WS;
            float acc = db[c];
            for (int dy = 0; dy < ksz; dy++) {
                int yy = iy + dy - pad;
                if (yy < 0 || yy >= WS) continue;
                for (int dx = 0; dx < ksz; dx++) {
                    int xx = ix + dx - pad;
                    if (xx < 0 || xx >= WS) continue;
                    acc += y[c * NTOK + yy * WS + xx] * dw[c * ksz * ksz + dy * ksz + dx];
                }
            }
            qc[o] = acc;
        }
        __syncthreads();
        for (int o = t; o < NTOK * NTOK; o += 256) {
            int n = o / NTOK, m = o % NTOK;
            float acc = 0.f;
#pragma unroll
            for (int c = 0; c < KD; c++) acc += qc[c * NTOK + n] * y[(KD + c) * NTOK + m];
            int ny = n / WS, nx = n % WS, my = m / WS, mx = m % WS;
            att[o] = acc * 0.25f + bia[abs(ny - my) * WS + abs(nx - mx)];
        }
        __syncthreads();
        if (t < NTOK) {
            float mx = -1e30f;
            for (int m = 0; m < NTOK; m++) mx = fmaxf(mx, att[t * NTOK + m]);
            float s = 0.f;
            for (int m = 0; m < NTOK; m++) { float e = expf(att[t * NTOK + m] - mx); att[t * NTOK + m] = e; s += e; }
            float inv = 1.f / s;
            for (int m = 0; m < NTOK; m++) att[t * NTOK + m] *= inv;
        }
        __syncthreads();
        size_t obase = (size_t)(head * DHEAD) * NPROJ + (size_t)w * NTOKP;
        for (int o = t; o < DHEAD * NTOK; o += 256) {
            int d = o / NTOK, n = o % NTOK;
            float acc = 0.f;
#pragma unroll 7
            for (int m = 0; m < NTOK; m++) acc += y[(2 * KD + d) * NTOK + m] * att[n * NTOK + m];
            ushort_t hh, ll;
            split2(hswish(acc), hh, ll);
            oh[obase + (size_t)d * NPROJ + n] = hh;
            ol[obase + (size_t)d * NPROJ + n] = ll;
            sp[o] = acc;
        }
        for (int o = t; o < DHEAD * (NTOKP - NTOK); o += 256) {
            int d = o / (NTOKP - NTOK), p = o % (NTOKP - NTOK);
            oh[obase + (size_t)d * NPROJ + NTOK + p] = 0;
            ol[obase + (size_t)d * NPROJ + NTOK + p] = 0;
        }
        __syncthreads();
    }
}

// ---------------------------------------------------------------------------
extern "C" void kernel_launch(void* const* d_in, const int* in_sizes, int n_in,
                              void* d_out, int out_size)
{
    const float* x        = (const float*)d_in[0];
    const float* dw0_w    = (const float*)d_in[1];
    const float* dw0_b    = (const float*)d_in[2];
    const float* ffn0_w1  = (const float*)d_in[3];
    const float* ffn0_b1  = (const float*)d_in[4];
    const float* ffn0_w2  = (const float*)d_in[5];
    const float* ffn0_b2  = (const float*)d_in[6];
    const float* qkv_w    = (const float*)d_in[7];
    const float* qkv_b    = (const float*)d_in[8];
    const float* dwq_w7   = (const float*)d_in[9];
    const float* dwq_b7   = (const float*)d_in[10];
    const float* dwq_w5   = (const float*)d_in[11];
    const float* dwq_b5   = (const float*)d_in[12];
    const float* dwq_w3   = (const float*)d_in[13];
    const float* dwq_b3   = (const float*)d_in[14];
    const float* attn_bias= (const float*)d_in[15];
    const float* proj_w   = (const float*)d_in[16];
    const float* proj_b   = (const float*)d_in[17];
    const float* dw1_w    = (const float*)d_in[18];
    const float* dw1_b    = (const float*)d_in[19];
    const float* ffn1_w1  = (const float*)d_in[20];
    const float* ffn1_b1  = (const float*)d_in[21];
    const float* ffn1_w2  = (const float*)d_in[22];
    const float* ffn1_b2  = (const float*)d_in[23];

    float *paf, *pbf;
    ushort_t *pah, *pal, *phh, *phl, *pch, *pcl;
    ushort_t *pw1h, *pw1l, *pw2h, *pw2l, *pw1bh, *pw1bl, *pw2bh, *pw2bl, *ppjh, *ppjl;
    cudaGetSymbolAddress((void**)&paf, g_af);
    cudaGetSymbolAddress((void**)&pbf, g_bf);
    cudaGetSymbolAddress((void**)&pah, g_ah);
    cudaGetSymbolAddress((void**)&pal, g_al);
    cudaGetSymbolAddress((void**)&phh, g_hh);
    cudaGetSymbolAddress((void**)&phl, g_hl);
    cudaGetSymbolAddress((void**)&pch, g_ch);
    cudaGetSymbolAddress((void**)&pcl, g_cl);
    cudaGetSymbolAddress((void**)&pw1h, g_w1h);
    cudaGetSymbolAddress((void**)&pw1l, g_w1l);
    cudaGetSymbolAddress((void**)&pw2h, g_w2h);
    cudaGetSymbolAddress((void**)&pw2l, g_w2l);
    cudaGetSymbolAddress((void**)&pw1bh, g_w1bh);
    cudaGetSymbolAddress((void**)&pw1bl, g_w1bl);
    cudaGetSymbolAddress((void**)&pw2bh, g_w2bh);
    cudaGetSymbolAddress((void**)&pw2bl, g_w2bl);
    cudaGetSymbolAddress((void**)&ppjh, g_pjh);
    cudaGetSymbolAddress((void**)&ppjl, g_pjl);

    cudaFuncSetAttribute(attn_kernel, cudaFuncAttributeMaxDynamicSharedMemorySize, ATTN_SMEM_BYTES);
    cudaFuncSetAttribute(gemm_cp_kernel<0>, cudaFuncAttributeMaxDynamicSharedMemorySize, 49152);
    cudaFuncSetAttribute(gemm_cp_kernel<1>, cudaFuncAttributeMaxDynamicSharedMemorySize, 49152);
    cudaFuncSetAttribute(gemm_cp_kernel<2>, cudaFuncAttributeMaxDynamicSharedMemorySize, 49152);
    cudaFuncSetAttribute(gemm_cp_kernel<3>, cudaFuncAttributeMaxDynamicSharedMemorySize, 49152);

    // Weight pre-split
    pack_weights_kernel<<<2048, 256>>>(ffn0_w1, pw1h, pw1l, 1024 * 512);
    pack_weights_kernel<<<2048, 256>>>(ffn0_w2, pw2h, pw2l, 512 * 1024);
    pack_weights_kernel<<<2048, 256>>>(ffn1_w1, pw1bh, pw1bl, 1024 * 512);
    pack_weights_kernel<<<2048, 256>>>(ffn1_w2, pw2bh, pw2bl, 512 * 1024);
    pack_weights_kernel<<<1024, 256>>>(proj_w, ppjh, ppjl, 512 * 512);

    dim3 dwgrid((HW + 255) / 256, BATCH * ED);

    // Stage 1: a = x + dwconv(x)
    dwconv_res_kernel<false><<<dwgrid, 256>>>(x, dw0_w, dw0_b, paf, pah, pal);
    // Stage 2: hidden planes = split(hswish(W1 a)); b = a + W2 h
    gemm_cp_kernel<0><<<dim3(NTOT / 64, 8), 256, 49152>>>(
        pw1h, pw1l, pah, pal, ffn0_b1, nullptr, nullptr, phh, phl, 1024, NTOT, 512);
    gemm_cp_kernel<1><<<dim3(NTOT / 64, 4), 256, 49152>>>(
        pw2h, pw2l, phh, phl, ffn0_b2, paf, pbf, nullptr, nullptr, 512, NTOT, 1024);
    // Stage 3: attention
    attn_kernel<<<NW_TOT, 256, ATTN_SMEM_BYTES>>>(pbf, qkv_w, qkv_b, dwq_w7, dwq_b7,
        dwq_w5, dwq_b5, dwq_w3, dwq_b3, attn_bias, pch, pcl);
    // Stage 4: proj + merge + residual (in-place into b)
    gemm_cp_kernel<2><<<dim3(NPROJ / 64, 4), 256, 49152>>>(
        ppjh, ppjl, pch, pcl, proj_b, nullptr, pbf, nullptr, nullptr, 512, NPROJ, 512);
    // Stage 5: a = b + dwconv(b)
    dwconv_res_kernel<true><<<dwgrid, 256>>>(pbf, dw1_w, dw1_b, paf, pah, pal);
    // Stage 6: hidden planes; out = a + W2' h (b-major store)
    gemm_cp_kernel<0><<<dim3(NTOT / 64, 8), 256, 49152>>>(
        pw1bh, pw1bl, pah, pal, ffn1_b1, nullptr, nullptr, phh, phl, 1024, NTOT, 512);
    gemm_cp_kernel<3><<<dim3(NTOT / 64, 4), 256, 49152>>>(
        pw2bh, pw2bl, phh, phl, ffn1_b2, paf, (float*)d_out, nullptr, nullptr, 512, NTOT, 1024);
}

// round 9
// speedup vs baseline: 4.7492x; 1.1618x over previous
#include <cuda_runtime.h>
#include <cuda_bf16.h>
#include <cstdint>
#include <cstring>
#include <math.h>

typedef unsigned short ushort_t;

// Shapes
#define BATCH 64
#define ED 512
#define RES 28
#define HW 784
#define WS 7
#define NW_TOT 1024
#define NH 8
#define KD 16
#define DHEAD 64
#define QKV_OUT 96
#define NTOK 49
#define NTOKP 56

#define NTOT 50176        // 64*784
#define NPROJ 57344       // 1024*56

// Scratch (device globals)
__device__ float    g_af[ED * NTOT];
__device__ float    g_bf[ED * NTOT];
__device__ ushort_t g_ah[ED * NTOT];
__device__ ushort_t g_al[ED * NTOT];
__device__ ushort_t g_hh[2 * ED * NTOT];
__device__ ushort_t g_hl[2 * ED * NTOT];
__device__ ushort_t g_ch[ED * NPROJ];
__device__ ushort_t g_cl[ED * NPROJ];
__device__ ushort_t g_w1h[1024 * 512], g_w1l[1024 * 512];
__device__ ushort_t g_w2h[512 * 1024], g_w2l[512 * 1024];
__device__ ushort_t g_w1bh[1024 * 512], g_w1bl[1024 * 512];
__device__ ushort_t g_w2bh[512 * 1024], g_w2bl[512 * 1024];
__device__ ushort_t g_pjh[512 * 512], g_pjl[512 * 512];

__device__ __forceinline__ float hswish(float x) {
    return x * fminf(fmaxf(x + 3.f, 0.f), 6.f) * (1.f / 6.f);
}
__device__ __forceinline__ void split2(float v, ushort_t& h, ushort_t& l) {
    __nv_bfloat16 hb = __float2bfloat16_rn(v);
    float hf = __bfloat162float(hb);
    __nv_bfloat16 lb = __float2bfloat16_rn(v - hf);
    memcpy(&h, &hb, 2);
    memcpy(&l, &lb, 2);
}
__device__ __forceinline__ uint32_t smem_u32(const void* p) {
    return (uint32_t)__cvta_generic_to_shared(p);
}
__device__ __forceinline__ void cpasync16(uint32_t dst, const void* src) {
    asm volatile("cp.async.cg.shared.global [%0], [%1], 16;" :: "r"(dst), "l"(src));
}
__device__ __forceinline__ void mma_bf16(float* c, const uint32_t* a, const uint32_t* b)
{
    asm volatile(
        "mma.sync.aligned.m16n8k16.row.col.f32.bf16.bf16.f32 "
        "{%0,%1,%2,%3}, {%4,%5,%6,%7}, {%8,%9}, {%0,%1,%2,%3};\n"
        : "+f"(c[0]), "+f"(c[1]), "+f"(c[2]), "+f"(c[3])
        : "r"(a[0]), "r"(a[1]), "r"(a[2]), "r"(a[3]), "r"(b[0]), "r"(b[1]));
}
__device__ __forceinline__ void ldsm4(uint32_t& r0, uint32_t& r1,
                                      uint32_t& r2, uint32_t& r3, uint32_t addr)
{
    asm volatile("ldmatrix.sync.aligned.m8n8.x4.shared.b16 {%0,%1,%2,%3}, [%4];"
                 : "=r"(r0), "=r"(r1), "=r"(r2), "=r"(r3) : "r"(addr));
}
__device__ __forceinline__ void ldsm4t(uint32_t& r0, uint32_t& r1,
                                       uint32_t& r2, uint32_t& r3, uint32_t addr)
{
    asm volatile("ldmatrix.sync.aligned.m8n8.x4.trans.shared.b16 {%0,%1,%2,%3}, [%4];"
                 : "=r"(r0), "=r"(r1), "=r"(r2), "=r"(r3) : "r"(addr));
}

// ---------------------------------------------------------------------------
__global__ void __launch_bounds__(256) pack_weights_kernel(
    const float* __restrict__ W, ushort_t* __restrict__ Ph,
    ushort_t* __restrict__ Pl, int n)
{
    int i = blockIdx.x * 256 + threadIdx.x;
    if (i < n) {
        ushort_t h, l;
        split2(W[i], h, l);
        Ph[i] = h; Pl[i] = l;
    }
}

// ---------------------------------------------------------------------------
template<bool IN_CM>
__global__ void __launch_bounds__(256) dwconv_res_kernel(
    const float* __restrict__ x, const float* __restrict__ w,
    const float* __restrict__ bias, float* __restrict__ out,
    ushort_t* __restrict__ oh, ushort_t* __restrict__ ol)
{
    int bc = blockIdx.y;
    int c = bc & (ED - 1);
    int b = bc >> 9;
    int pos = blockIdx.x * 256 + threadIdx.x;
    if (pos >= HW) return;
    int h = pos / RES, ww = pos % RES;
    const float* xp = IN_CM ? (x + (size_t)c * NTOT + (size_t)b * HW)
                            : (x + (size_t)bc * HW);
    const float* wp = w + c * 9;
    float acc = bias[c];
#pragma unroll
    for (int dy = 0; dy < 3; dy++) {
        int yy = h + dy - 1;
        if (yy < 0 || yy >= RES) continue;
#pragma unroll
        for (int dx = 0; dx < 3; dx++) {
            int xx = ww + dx - 1;
            if (xx < 0 || xx >= RES) continue;
            acc += xp[yy * RES + xx] * wp[dy * 3 + dx];
        }
    }
    float r = xp[pos] + acc;
    size_t o = (size_t)c * NTOT + (size_t)b * HW + pos;
    out[o] = r;
    ushort_t hh, ll;
    split2(r, hh, ll);
    oh[o] = hh; ol[o] = ll;
}

// ---------------------------------------------------------------------------
// HMMA GEMM, CTA 128x128, K-chunk 32, cp.async double buffer, hi/lo planes.
// Warps: 2 along M (64 rows) x 4 along N (32 cols).
// Stage layout (32KB): Ah 0 | Al 8K | Bh 16K | Bl 24K. Two stages = 64KB.
// MODE 0: hidden planes = split(hswish(v+bias))
// MODE 1: Cf = v+bias+resid (c-major)
// MODE 2: proj+merge: Cf[spatial] += v+bias (tok<49)
// MODE 3: final: out[b][m][pos] = v+bias+resid
// ---------------------------------------------------------------------------
template<int MODE>
__global__ void __launch_bounds__(256, 2) gemm_cp_kernel(
    const ushort_t* __restrict__ Awh, const ushort_t* __restrict__ Awl,
    const ushort_t* __restrict__ Bh,  const ushort_t* __restrict__ Bl,
    const float* __restrict__ bias, const float* __restrict__ resid,
    float* __restrict__ Cf, ushort_t* __restrict__ Chh, ushort_t* __restrict__ Chl,
    int M, int NB, int K)
{
    extern __shared__ char sm[];
    int t = threadIdx.x;
    int warp = t >> 5, lane = t & 31;
    int wm = warp & 1, wn = warp >> 1;
    int m0w = wm * 64, n0w = wn * 32;
    int g = lane >> 2, tig = lane & 3;
    int m0 = blockIdx.y * 128, n0 = blockIdx.x * 128;
    uint32_t sbase = smem_u32(sm);

    float acc[4][4][4];
#pragma unroll
    for (int i = 0; i < 4; i++)
#pragma unroll
        for (int j = 0; j < 4; j++)
#pragma unroll
            for (int q = 0; q < 4; q++) acc[i][j][q] = 0.f;

    auto stage = [&](int k0, int buf) {
        uint32_t soff = sbase + buf * 32768;
        // A: 128 m x 32 k per plane = 512 x 16B chunks
#pragma unroll
        for (int i = 0; i < 2; i++) {
            int idx = t + i * 256;
            int m = idx >> 2, c = idx & 3;
            uint32_t d = soff + m * 64 + ((c ^ ((m >> 1) & 3)) << 4);
            cpasync16(d, Awh + (size_t)(m0 + m) * K + k0 + c * 8);
            cpasync16(d + 8192, Awl + (size_t)(m0 + m) * K + k0 + c * 8);
        }
        // B: 32 k x 128 n per plane = 512 x 16B chunks
#pragma unroll
        for (int i = 0; i < 2; i++) {
            int idx = t + i * 256;
            int k = idx >> 4, c = idx & 15;
            uint32_t d = soff + 16384 + k * 256 + ((c ^ (k & 7)) << 4);
            cpasync16(d, Bh + (size_t)(k0 + k) * NB + n0 + c * 8);
            cpasync16(d + 8192, Bl + (size_t)(k0 + k) * NB + n0 + c * 8);
        }
        asm volatile("cp.async.commit_group;" ::: "memory");
    };

    stage(0, 0);
    int nk = K >> 5;
    for (int kc = 0; kc < nk; kc++) {
        if (kc + 1 < nk) {
            stage((kc + 1) << 5, (kc + 1) & 1);
            asm volatile("cp.async.wait_group 1;" ::: "memory");
        } else {
            asm volatile("cp.async.wait_group 0;" ::: "memory");
        }
        __syncthreads();
        uint32_t soff = sbase + (kc & 1) * 32768;
#pragma unroll
        for (int kk = 0; kk < 32; kk += 16) {
            uint32_t ah[4][4], al[4][4], bh[4][2], bl[4][2];
#pragma unroll
            for (int i = 0; i < 4; i++) {
                int row = m0w + i * 16 + (lane & 15);
                int c = (kk >> 3) + (lane >> 4);
                uint32_t a = soff + row * 64 + ((c ^ ((row >> 1) & 3)) << 4);
                ldsm4(ah[i][0], ah[i][1], ah[i][2], ah[i][3], a);
                ldsm4(al[i][0], al[i][1], al[i][2], al[i][3], a + 8192);
            }
#pragma unroll
            for (int j2 = 0; j2 < 2; j2++) {
                int krow = kk + (lane & 15);
                int cn = wn * 4 + j2 * 2 + (lane >> 4);
                uint32_t a = soff + 16384 + krow * 256 + ((cn ^ (krow & 7)) << 4);
                ldsm4t(bh[j2*2][0], bh[j2*2][1], bh[j2*2+1][0], bh[j2*2+1][1], a);
                ldsm4t(bl[j2*2][0], bl[j2*2][1], bl[j2*2+1][0], bl[j2*2+1][1], a + 8192);
            }
#pragma unroll
            for (int i = 0; i < 4; i++)
#pragma unroll
                for (int j = 0; j < 4; j++) {
                    mma_bf16(acc[i][j], ah[i], bh[j]);
                    mma_bf16(acc[i][j], ah[i], bl[j]);
                    mma_bf16(acc[i][j], al[i], bh[j]);
                }
        }
        __syncthreads();
    }

    // Epilogue
#pragma unroll
    for (int i = 0; i < 4; i++) {
        int r0 = m0 + m0w + i * 16 + g;
        int r1 = r0 + 8;
        float b0v = bias[r0], b1v = bias[r1];
#pragma unroll
        for (int j = 0; j < 4; j++) {
            int cb = n0 + n0w + j * 8 + tig * 2;
            float v00 = acc[i][j][0] + b0v, v01 = acc[i][j][1] + b0v;
            float v10 = acc[i][j][2] + b1v, v11 = acc[i][j][3] + b1v;
            if (MODE == 0) {
                ushort_t h0, l0, h1, l1;
                split2(hswish(v00), h0, l0);
                split2(hswish(v01), h1, l1);
                *(uint32_t*)&Chh[(size_t)r0 * NB + cb] = (uint32_t)h0 | ((uint32_t)h1 << 16);
                *(uint32_t*)&Chl[(size_t)r0 * NB + cb] = (uint32_t)l0 | ((uint32_t)l1 << 16);
                split2(hswish(v10), h0, l0);
                split2(hswish(v11), h1, l1);
                *(uint32_t*)&Chh[(size_t)r1 * NB + cb] = (uint32_t)h0 | ((uint32_t)h1 << 16);
                *(uint32_t*)&Chl[(size_t)r1 * NB + cb] = (uint32_t)l0 | ((uint32_t)l1 << 16);
            } else if (MODE == 1) {
                size_t o0 = (size_t)r0 * NB + cb;
                size_t o1 = (size_t)r1 * NB + cb;
                float2 rr0 = *(const float2*)&resid[o0];
                float2 rr1 = *(const float2*)&resid[o1];
                *(float2*)&Cf[o0] = make_float2(v00 + rr0.x, v01 + rr0.y);
                *(float2*)&Cf[o1] = make_float2(v10 + rr1.x, v11 + rr1.y);
            } else if (MODE == 2) {
                float vs[4] = {v00, v01, v10, v11};
#pragma unroll
                for (int q = 0; q < 4; q++) {
                    int col = cb + (q & 1);
                    int r = (q < 2) ? r0 : r1;
                    int win = col / NTOKP, tok = col % NTOKP;
                    if (tok < NTOK) {
                        int b = win >> 4, wy = (win >> 2) & 3, wx = win & 3;
                        int iy = tok / WS, ix = tok % WS;
                        size_t o = (size_t)r * NTOT + (size_t)b * HW
                                 + (wy * WS + iy) * RES + (wx * WS + ix);
                        Cf[o] = Cf[o] + vs[q];
                    }
                }
            } else {
                int b = cb / HW, pos = cb % HW;
                size_t o0 = (size_t)r0 * NB + cb;
                size_t o1 = (size_t)r1 * NB + cb;
                float2 rr0 = *(const float2*)&resid[o0];
                float2 rr1 = *(const float2*)&resid[o1];
                *(float2*)&Cf[((size_t)b * ED + r0) * HW + pos] =
                    make_float2(v00 + rr0.x, v01 + rr0.y);
                *(float2*)&Cf[((size_t)b * ED + r1) * HW + pos] =
                    make_float2(v10 + rr1.x, v11 + rr1.y);
            }
        }
    }
}

// ---------------------------------------------------------------------------
// Cascaded window attention, vectorized. Token-major spT; float4 dots.
// smem (floats): spT[49][68] | y[96][52] | kT[49][20] | qcT[49][20]
//              | att[49][52] | wsm[96][68] | bsm[96] | bia[64]
// ---------------------------------------------------------------------------
#define SP_OFF   0
#define Y_OFF    (SP_OFF + 49 * 68)          // 3332
#define KT_OFF   (Y_OFF + 96 * 52)           // +4992
#define QT_OFF   (KT_OFF + 49 * 20)          // +980
#define ATT_OFF  (QT_OFF + 49 * 20)          // +980
#define WSM_OFF  (ATT_OFF + 49 * 52)         // +2548
#define BSM_OFF  (WSM_OFF + 96 * 68)         // +6528
#define BIA_OFF  (BSM_OFF + 96)
#define ATTN_SMEM_FLOATS (BIA_OFF + 64)
#define ATTN_SMEM_BYTES  (ATTN_SMEM_FLOATS * 4)

__global__ void __launch_bounds__(256) attn_kernel(
    const float* __restrict__ xin,
    const float* __restrict__ qkv_w,
    const float* __restrict__ qkv_b,
    const float* __restrict__ w7, const float* __restrict__ b7,
    const float* __restrict__ w5, const float* __restrict__ b5,
    const float* __restrict__ w3, const float* __restrict__ b3,
    const float* __restrict__ attn_bias,
    ushort_t* __restrict__ oh, ushort_t* __restrict__ ol)
{
    extern __shared__ float smem[];
    float* spT = smem + SP_OFF;
    float* y   = smem + Y_OFF;
    float* kT  = smem + KT_OFF;
    float* qcT = smem + QT_OFF;
    float* att = smem + ATT_OFF;
    float* wsm = smem + WSM_OFF;
    float* bsm = smem + BSM_OFF;
    float* bia = smem + BIA_OFF;

    int w = blockIdx.x;
    int b = w >> 4, wy = (w >> 2) & 3, wx = w & 3;
    int t = threadIdx.x;
    int warp = t >> 5, lane = t & 31;

    // Zero v-row column pads (y[*][49..51]) once.
    for (int i = t; i < 96 * 3; i += 256)
        y[(i / 3) * 52 + 49 + i % 3] = 0.f;

    for (int head = 0; head < NH; head++) {
        // stage weights (padded rows) + biases + cascade update
        for (int i = t; i < QKV_OUT * DHEAD; i += 256) {
            int m = i >> 6, c = i & 63;
            wsm[m * 68 + c] = qkv_w[head * QKV_OUT * DHEAD + i];
        }
        if (t < QKV_OUT) bsm[t] = qkv_b[head * QKV_OUT + t];
        if (t < NTOK)    bia[t] = attn_bias[head * NTOK + t];
        for (int i = t; i < DHEAD * NTOK; i += 256) {
            int c = i / NTOK, n = i % NTOK;
            int iy = n / WS, ix = n % WS;
            float xv = xin[(size_t)(head * DHEAD + c) * NTOT + (size_t)b * HW
                           + (wy * WS + iy) * RES + (wx * WS + ix)];
            spT[n * 68 + c] = (head == 0) ? xv : spT[n * 68 + c] + xv;
        }
        __syncthreads();

        // QKV: y[m][n] = bsm[m] + dot(wsm[m][:], spT[n][:]); also kT
        for (int it = t; it < 13 * 96; it += 256) {
            int gq = it / 96, m = it % 96;
            int n0 = gq * 4;
            float a0 = bsm[m], a1 = a0, a2 = a0, a3 = a0;
            const float* wr = &wsm[m * 68];
#pragma unroll
            for (int c4 = 0; c4 < 16; c4++) {
                float4 wv = *(const float4*)&wr[c4 * 4];
                float4 s0 = *(const float4*)&spT[(n0 + 0) * 68 + c4 * 4];
                float4 s1 = *(const float4*)&spT[(n0 + 1) * 68 + c4 * 4];
                float4 s2 = *(const float4*)&spT[(n0 + 2) * 68 + c4 * 4];
                float4 s3 = *(const float4*)&spT[(n0 + 3) * 68 + c4 * 4];
                a0 += wv.x * s0.x + wv.y * s0.y + wv.z * s0.z + wv.w * s0.w;
                a1 += wv.x * s1.x + wv.y * s1.y + wv.z * s1.z + wv.w * s1.w;
                a2 += wv.x * s2.x + wv.y * s2.y + wv.z * s2.z + wv.w * s2.w;
                a3 += wv.x * s3.x + wv.y * s3.y + wv.z * s3.z + wv.w * s3.w;
            }
            float av[4] = {a0, a1, a2, a3};
#pragma unroll
            for (int j = 0; j < 4; j++) {
                int n = n0 + j;
                if (n < NTOK) {
                    y[m * 52 + n] = av[j];
                    if (m >= KD && m < 2 * KD) kT[n * 20 + m - KD] = av[j];
                }
            }
        }
        __syncthreads();

        // depthwise conv on q -> qcT[n][c]
        int ksz; const float* dw; const float* db;
        if (head == 0)      { ksz = 7; dw = w7; db = b7; }
        else if (head == 1) { ksz = 5; dw = w5; db = b5; }
        else                { ksz = 3; dw = w3 + (head - 2) * KD * 9; db = b3 + (head - 2) * KD; }
        int pad = ksz >> 1;
        for (int it = t; it < KD * NTOK; it += 256) {
            int c = it / NTOK, n = it % NTOK;
            int iy = n / WS, ix = n % WS;
            float acc = db[c];
            const float* yr = &y[c * 52];
            const float* dwc = dw + c * ksz * ksz;
            for (int dy = 0; dy < ksz; dy++) {
                int yy = iy + dy - pad;
                if (yy < 0 || yy >= WS) continue;
                for (int dx = 0; dx < ksz; dx++) {
                    int xx = ix + dx - pad;
                    if (xx < 0 || xx >= WS) continue;
                    acc += yr[yy * WS + xx] * dwc[dy * ksz + dx];
                }
            }
            qcT[n * 20 + c] = acc;
        }
        __syncthreads();

        // scores: att[n][m] (m<49), pad cols 49..51 zero
        for (int it = t; it < 49 * 52; it += 256) {
            int n = it / 52, m = it % 52;
            if (m >= NTOK) { att[it] = 0.f; continue; }
            const float* qr = &qcT[n * 20];
            const float* kr = &kT[m * 20];
            float acc = 0.f;
#pragma unroll
            for (int c4 = 0; c4 < 4; c4++) {
                float4 qv = *(const float4*)&qr[c4 * 4];
                float4 kv = *(const float4*)&kr[c4 * 4];
                acc += qv.x * kv.x + qv.y * kv.y + qv.z * kv.z + qv.w * kv.w;
            }
            int ny = n / WS, nx = n % WS, my = m / WS, mx = m % WS;
            att[it] = acc * 0.25f + bia[abs(ny - my) * WS + abs(nx - mx)];
        }
        __syncthreads();

        // softmax: warp per row
        for (int r = warp; r < NTOK; r += 8) {
            float v0 = att[r * 52 + lane];
            float v1 = (lane + 32 < NTOK) ? att[r * 52 + lane + 32] : -1e30f;
            float mx = fmaxf(v0, v1);
#pragma unroll
            for (int s = 16; s; s >>= 1) mx = fmaxf(mx, __shfl_xor_sync(~0u, mx, s));
            float e0 = expf(v0 - mx);
            float e1 = (lane + 32 < NTOK) ? expf(v1 - mx) : 0.f;
            float sum = e0 + e1;
#pragma unroll
            for (int s = 16; s; s >>= 1) sum += __shfl_xor_sync(~0u, sum, s);
            float inv = 1.f / sum;
            att[r * 52 + lane] = e0 * inv;
            if (lane + 32 < NTOK) att[r * 52 + lane + 32] = e1 * inv;
        }
        __syncthreads();

        // AV: out[d][n] = dot(v[d][:], att[n][:]); v rows y[32+d], att pads 0
        size_t obase = (size_t)(head * DHEAD) * NPROJ + (size_t)w * NTOKP;
        for (int it = t; it < 16 * NTOK; it += 256) {
            int dg = it / NTOK, n = it % NTOK;
            int d0 = dg * 4;
            float a0 = 0.f, a1 = 0.f, a2 = 0.f, a3 = 0.f;
            const float* ar = &att[n * 52];
#pragma unroll
            for (int m4 = 0; m4 < 13; m4++) {
                float4 av = *(const float4*)&ar[m4 * 4];
                float4 v0 = *(const float4*)&y[(32 + d0 + 0) * 52 + m4 * 4];
                float4 v1 = *(const float4*)&y[(32 + d0 + 1) * 52 + m4 * 4];
                float4 v2 = *(const float4*)&y[(32 + d0 + 2) * 52 + m4 * 4];
                float4 v3 = *(const float4*)&y[(32 + d0 + 3) * 52 + m4 * 4];
                a0 += av.x * v0.x + av.y * v0.y + av.z * v0.z + av.w * v0.w;
                a1 += av.x * v1.x + av.y * v1.y + av.z * v1.z + av.w * v1.w;
                a2 += av.x * v2.x + av.y * v2.y + av.z * v2.z + av.w * v2.w;
                a3 += av.x * v3.x + av.y * v3.y + av.z * v3.z + av.w * v3.w;
            }
            float av4[4] = {a0, a1, a2, a3};
#pragma unroll
            for (int jj = 0; jj < 4; jj++) {
                int d = d0 + jj;
                spT[n * 68 + d] = av4[jj];
                ushort_t hh, ll;
                split2(hswish(av4[jj]), hh, ll);
                oh[obase + (size_t)d * NPROJ + n] = hh;
                ol[obase + (size_t)d * NPROJ + n] = ll;
            }
        }
        // zero pad token cols 49..55
        for (int it = t; it < DHEAD * (NTOKP - NTOK); it += 256) {
            int d = it / (NTOKP - NTOK), p = it % (NTOKP - NTOK);
            oh[obase + (size_t)d * NPROJ + NTOK + p] = 0;
            ol[obase + (size_t)d * NPROJ + NTOK + p] = 0;
        }
        __syncthreads();
    }
}

// ---------------------------------------------------------------------------
extern "C" void kernel_launch(void* const* d_in, const int* in_sizes, int n_in,
                              void* d_out, int out_size)
{
    const float* x        = (const float*)d_in[0];
    const float* dw0_w    = (const float*)d_in[1];
    const float* dw0_b    = (const float*)d_in[2];
    const float* ffn0_w1  = (const float*)d_in[3];
    const float* ffn0_b1  = (const float*)d_in[4];
    const float* ffn0_w2  = (const float*)d_in[5];
    const float* ffn0_b2  = (const float*)d_in[6];
    const float* qkv_w    = (const float*)d_in[7];
    const float* qkv_b    = (const float*)d_in[8];
    const float* dwq_w7   = (const float*)d_in[9];
    const float* dwq_b7   = (const float*)d_in[10];
    const float* dwq_w5   = (const float*)d_in[11];
    const float* dwq_b5   = (const float*)d_in[12];
    const float* dwq_w3   = (const float*)d_in[13];
    const float* dwq_b3   = (const float*)d_in[14];
    const float* attn_bias= (const float*)d_in[15];
    const float* proj_w   = (const float*)d_in[16];
    const float* proj_b   = (const float*)d_in[17];
    const float* dw1_w    = (const float*)d_in[18];
    const float* dw1_b    = (const float*)d_in[19];
    const float* ffn1_w1  = (const float*)d_in[20];
    const float* ffn1_b1  = (const float*)d_in[21];
    const float* ffn1_w2  = (const float*)d_in[22];
    const float* ffn1_b2  = (const float*)d_in[23];

    float *paf, *pbf;
    ushort_t *pah, *pal, *phh, *phl, *pch, *pcl;
    ushort_t *pw1h, *pw1l, *pw2h, *pw2l, *pw1bh, *pw1bl, *pw2bh, *pw2bl, *ppjh, *ppjl;
    cudaGetSymbolAddress((void**)&paf, g_af);
    cudaGetSymbolAddress((void**)&pbf, g_bf);
    cudaGetSymbolAddress((void**)&pah, g_ah);
    cudaGetSymbolAddress((void**)&pal, g_al);
    cudaGetSymbolAddress((void**)&phh, g_hh);
    cudaGetSymbolAddress((void**)&phl, g_hl);
    cudaGetSymbolAddress((void**)&pch, g_ch);
    cudaGetSymbolAddress((void**)&pcl, g_cl);
    cudaGetSymbolAddress((void**)&pw1h, g_w1h);
    cudaGetSymbolAddress((void**)&pw1l, g_w1l);
    cudaGetSymbolAddress((void**)&pw2h, g_w2h);
    cudaGetSymbolAddress((void**)&pw2l, g_w2l);
    cudaGetSymbolAddress((void**)&pw1bh, g_w1bh);
    cudaGetSymbolAddress((void**)&pw1bl, g_w1bl);
    cudaGetSymbolAddress((void**)&pw2bh, g_w2bh);
    cudaGetSymbolAddress((void**)&pw2bl, g_w2bl);
    cudaGetSymbolAddress((void**)&ppjh, g_pjh);
    cudaGetSymbolAddress((void**)&ppjl, g_pjl);

    cudaFuncSetAttribute(attn_kernel, cudaFuncAttributeMaxDynamicSharedMemorySize, ATTN_SMEM_BYTES);
    cudaFuncSetAttribute(gemm_cp_kernel<0>, cudaFuncAttributeMaxDynamicSharedMemorySize, 65536);
    cudaFuncSetAttribute(gemm_cp_kernel<1>, cudaFuncAttributeMaxDynamicSharedMemorySize, 65536);
    cudaFuncSetAttribute(gemm_cp_kernel<2>, cudaFuncAttributeMaxDynamicSharedMemorySize, 65536);
    cudaFuncSetAttribute(gemm_cp_kernel<3>, cudaFuncAttributeMaxDynamicSharedMemorySize, 65536);

    // Weight pre-split
    pack_weights_kernel<<<2048, 256>>>(ffn0_w1, pw1h, pw1l, 1024 * 512);
    pack_weights_kernel<<<2048, 256>>>(ffn0_w2, pw2h, pw2l, 512 * 1024);
    pack_weights_kernel<<<2048, 256>>>(ffn1_w1, pw1bh, pw1bl, 1024 * 512);
    pack_weights_kernel<<<2048, 256>>>(ffn1_w2, pw2bh, pw2bl, 512 * 1024);
    pack_weights_kernel<<<1024, 256>>>(proj_w, ppjh, ppjl, 512 * 512);

    dim3 dwgrid((HW + 255) / 256, BATCH * ED);

    // Stage 1: a = x + dwconv(x)
    dwconv_res_kernel<false><<<dwgrid, 256>>>(x, dw0_w, dw0_b, paf, pah, pal);
    // Stage 2: hidden planes = split(hswish(W1 a)); b = a + W2 h
    gemm_cp_kernel<0><<<dim3(NTOT / 128, 8), 256, 65536>>>(
        pw1h, pw1l, pah, pal, ffn0_b1, nullptr, nullptr, phh, phl, 1024, NTOT, 512);
    gemm_cp_kernel<1><<<dim3(NTOT / 128, 4), 256, 65536>>>(
        pw2h, pw2l, phh, phl, ffn0_b2, paf, pbf, nullptr, nullptr, 512, NTOT, 1024);
    // Stage 3: attention
    attn_kernel<<<NW_TOT, 256, ATTN_SMEM_BYTES>>>(pbf, qkv_w, qkv_b, dwq_w7, dwq_b7,
        dwq_w5, dwq_b5, dwq_w3, dwq_b3, attn_bias, pch, pcl);
    // Stage 4: proj + merge + residual (in-place into b)
    gemm_cp_kernel<2><<<dim3(NPROJ / 128, 4), 256, 65536>>>(
        ppjh, ppjl, pch, pcl, proj_b, nullptr, pbf, nullptr, nullptr, 512, NPROJ, 512);
    // Stage 5: a = b + dwconv(b)
    dwconv_res_kernel<true><<<dwgrid, 256>>>(pbf, dw1_w, dw1_b, paf, pah, pal);
    // Stage 6: hidden planes; out = a + W2' h (b-major store)
    gemm_cp_kernel<0><<<dim3(NTOT / 128, 8), 256, 65536>>>(
        pw1bh, pw1bl, pah, pal, ffn1_b1, nullptr, nullptr, phh, phl, 1024, NTOT, 512);
    gemm_cp_kernel<3><<<dim3(NTOT / 128, 4), 256, 65536>>>(
        pw2bh, pw2bl, phh, phl, ffn1_b2, paf, (float*)d_out, nullptr, nullptr, 512, NTOT, 1024);
}

// round 10
// speedup vs baseline: 4.7500x; 1.0002x over previous
#include <cuda_runtime.h>
#include <cuda_bf16.h>
#include <cstdint>
#include <cstring>
#include <math.h>

typedef unsigned short ushort_t;

// Shapes
#define BATCH 64
#define ED 512
#define RES 28
#define HW 784
#define WS 7
#define NW_TOT 1024
#define NH 8
#define KD 16
#define DHEAD 64
#define QKV_OUT 96
#define NTOK 49
#define NTOKP 56

#define NTOT 50176        // 64*784
#define NPROJ 57344       // 1024*56

// Scratch (device globals)
__device__ float    g_af[ED * NTOT];
__device__ float    g_bf[ED * NTOT];
__device__ ushort_t g_ah[ED * NTOT];
__device__ ushort_t g_al[ED * NTOT];
__device__ ushort_t g_hh[2 * ED * NTOT];
__device__ ushort_t g_hl[2 * ED * NTOT];
__device__ ushort_t g_ch[ED * NPROJ];
__device__ ushort_t g_cl[ED * NPROJ];
__device__ ushort_t g_w1h[1024 * 512], g_w1l[1024 * 512];
__device__ ushort_t g_w2h[512 * 1024], g_w2l[512 * 1024];
__device__ ushort_t g_w1bh[1024 * 512], g_w1bl[1024 * 512];
__device__ ushort_t g_w2bh[512 * 1024], g_w2bl[512 * 1024];
__device__ ushort_t g_pjh[512 * 512], g_pjl[512 * 512];

__device__ __forceinline__ float hswish(float x) {
    return x * fminf(fmaxf(x + 3.f, 0.f), 6.f) * (1.f / 6.f);
}
__device__ __forceinline__ void split2(float v, ushort_t& h, ushort_t& l) {
    __nv_bfloat16 hb = __float2bfloat16_rn(v);
    float hf = __bfloat162float(hb);
    __nv_bfloat16 lb = __float2bfloat16_rn(v - hf);
    memcpy(&h, &hb, 2);
    memcpy(&l, &lb, 2);
}
__device__ __forceinline__ uint32_t smem_u32(const void* p) {
    return (uint32_t)__cvta_generic_to_shared(p);
}
__device__ __forceinline__ void cpasync16(uint32_t dst, const void* src) {
    asm volatile("cp.async.cg.shared.global [%0], [%1], 16;" :: "r"(dst), "l"(src));
}
__device__ __forceinline__ void mma_bf16(float* c, const uint32_t* a, const uint32_t* b)
{
    asm volatile(
        "mma.sync.aligned.m16n8k16.row.col.f32.bf16.bf16.f32 "
        "{%0,%1,%2,%3}, {%4,%5,%6,%7}, {%8,%9}, {%0,%1,%2,%3};\n"
        : "+f"(c[0]), "+f"(c[1]), "+f"(c[2]), "+f"(c[3])
        : "r"(a[0]), "r"(a[1]), "r"(a[2]), "r"(a[3]), "r"(b[0]), "r"(b[1]));
}
__device__ __forceinline__ void ldsm4(uint32_t& r0, uint32_t& r1,
                                      uint32_t& r2, uint32_t& r3, uint32_t addr)
{
    asm volatile("ldmatrix.sync.aligned.m8n8.x4.shared.b16 {%0,%1,%2,%3}, [%4];"
                 : "=r"(r0), "=r"(r1), "=r"(r2), "=r"(r3) : "r"(addr));
}
__device__ __forceinline__ void ldsm4t(uint32_t& r0, uint32_t& r1,
                                       uint32_t& r2, uint32_t& r3, uint32_t addr)
{
    asm volatile("ldmatrix.sync.aligned.m8n8.x4.trans.shared.b16 {%0,%1,%2,%3}, [%4];"
                 : "=r"(r0), "=r"(r1), "=r"(r2), "=r"(r3) : "r"(addr));
}

// ---------------------------------------------------------------------------
__global__ void __launch_bounds__(256) pack_weights_kernel(
    const float* __restrict__ W, ushort_t* __restrict__ Ph,
    ushort_t* __restrict__ Pl, int n)
{
    int i = blockIdx.x * 256 + threadIdx.x;
    if (i < n) {
        ushort_t h, l;
        split2(W[i], h, l);
        Ph[i] = h; Pl[i] = l;
    }
}

// ---------------------------------------------------------------------------
template<bool IN_CM>
__global__ void __launch_bounds__(256) dwconv_res_kernel(
    const float* __restrict__ x, const float* __restrict__ w,
    const float* __restrict__ bias, float* __restrict__ out,
    ushort_t* __restrict__ oh, ushort_t* __restrict__ ol)
{
    int bc = blockIdx.y;
    int c = bc & (ED - 1);
    int b = bc >> 9;
    int pos = blockIdx.x * 256 + threadIdx.x;
    if (pos >= HW) return;
    int h = pos / RES, ww = pos % RES;
    const float* xp = IN_CM ? (x + (size_t)c * NTOT + (size_t)b * HW)
                            : (x + (size_t)bc * HW);
    const float* wp = w + c * 9;
    float acc = bias[c];
#pragma unroll
    for (int dy = 0; dy < 3; dy++) {
        int yy = h + dy - 1;
        if (yy < 0 || yy >= RES) continue;
#pragma unroll
        for (int dx = 0; dx < 3; dx++) {
            int xx = ww + dx - 1;
            if (xx < 0 || xx >= RES) continue;
            acc += xp[yy * RES + xx] * wp[dy * 3 + dx];
        }
    }
    float r = xp[pos] + acc;
    size_t o = (size_t)c * NTOT + (size_t)b * HW + pos;
    out[o] = r;
    ushort_t hh, ll;
    split2(r, hh, ll);
    oh[o] = hh; ol[o] = ll;
}

// ---------------------------------------------------------------------------
// HMMA GEMM, CTA 128x128, K-chunk 32, cp.async double buffer, hi/lo planes.
// A-fragments loaded per m-subtile inside the mma loop to keep regs < 128.
// ---------------------------------------------------------------------------
template<int MODE>
__global__ void __launch_bounds__(256, 2) gemm_cp_kernel(
    const ushort_t* __restrict__ Awh, const ushort_t* __restrict__ Awl,
    const ushort_t* __restrict__ Bh,  const ushort_t* __restrict__ Bl,
    const float* __restrict__ bias, const float* __restrict__ resid,
    float* __restrict__ Cf, ushort_t* __restrict__ Chh, ushort_t* __restrict__ Chl,
    int M, int NB, int K)
{
    extern __shared__ char sm[];
    int t = threadIdx.x;
    int warp = t >> 5, lane = t & 31;
    int wm = warp & 1, wn = warp >> 1;
    int m0w = wm * 64, n0w = wn * 32;
    int g = lane >> 2, tig = lane & 3;
    int m0 = blockIdx.y * 128, n0 = blockIdx.x * 128;
    uint32_t sbase = smem_u32(sm);

    float acc[4][4][4];
#pragma unroll
    for (int i = 0; i < 4; i++)
#pragma unroll
        for (int j = 0; j < 4; j++)
#pragma unroll
            for (int q = 0; q < 4; q++) acc[i][j][q] = 0.f;

    auto stage = [&](int k0, int buf) {
        uint32_t soff = sbase + buf * 32768;
#pragma unroll
        for (int i = 0; i < 2; i++) {
            int idx = t + i * 256;
            int m = idx >> 2, c = idx & 3;
            uint32_t d = soff + m * 64 + ((c ^ ((m >> 1) & 3)) << 4);
            cpasync16(d, Awh + (size_t)(m0 + m) * K + k0 + c * 8);
            cpasync16(d + 8192, Awl + (size_t)(m0 + m) * K + k0 + c * 8);
        }
#pragma unroll
        for (int i = 0; i < 2; i++) {
            int idx = t + i * 256;
            int k = idx >> 4, c = idx & 15;
            uint32_t d = soff + 16384 + k * 256 + ((c ^ (k & 7)) << 4);
            cpasync16(d, Bh + (size_t)(k0 + k) * NB + n0 + c * 8);
            cpasync16(d + 8192, Bl + (size_t)(k0 + k) * NB + n0 + c * 8);
        }
        asm volatile("cp.async.commit_group;" ::: "memory");
    };

    stage(0, 0);
    int nk = K >> 5;
    for (int kc = 0; kc < nk; kc++) {
        if (kc + 1 < nk) {
            stage((kc + 1) << 5, (kc + 1) & 1);
            asm volatile("cp.async.wait_group 1;" ::: "memory");
        } else {
            asm volatile("cp.async.wait_group 0;" ::: "memory");
        }
        __syncthreads();
        uint32_t soff = sbase + (kc & 1) * 32768;
#pragma unroll
        for (int kk = 0; kk < 32; kk += 16) {
            // B fragments first (live across whole kk step: 16 regs)
            uint32_t bh[4][2], bl[4][2];
#pragma unroll
            for (int j2 = 0; j2 < 2; j2++) {
                int krow = kk + (lane & 15);
                int cn = wn * 4 + j2 * 2 + (lane >> 4);
                uint32_t a = soff + 16384 + krow * 256 + ((cn ^ (krow & 7)) << 4);
                ldsm4t(bh[j2*2][0], bh[j2*2][1], bh[j2*2+1][0], bh[j2*2+1][1], a);
                ldsm4t(bl[j2*2][0], bl[j2*2][1], bl[j2*2+1][0], bl[j2*2+1][1], a + 8192);
            }
            // A fragments loaded per m-subtile (8 regs live at a time)
#pragma unroll
            for (int i = 0; i < 4; i++) {
                int row = m0w + i * 16 + (lane & 15);
                int c = (kk >> 3) + (lane >> 4);
                uint32_t a = soff + row * 64 + ((c ^ ((row >> 1) & 3)) << 4);
                uint32_t ah[4], al[4];
                ldsm4(ah[0], ah[1], ah[2], ah[3], a);
                ldsm4(al[0], al[1], al[2], al[3], a + 8192);
#pragma unroll
                for (int j = 0; j < 4; j++) {
                    mma_bf16(acc[i][j], ah, bh[j]);
                    mma_bf16(acc[i][j], ah, bl[j]);
                    mma_bf16(acc[i][j], al, bh[j]);
                }
            }
        }
        __syncthreads();
    }

    // Epilogue
#pragma unroll
    for (int i = 0; i < 4; i++) {
        int r0 = m0 + m0w + i * 16 + g;
        int r1 = r0 + 8;
        float b0v = bias[r0], b1v = bias[r1];
#pragma unroll
        for (int j = 0; j < 4; j++) {
            int cb = n0 + n0w + j * 8 + tig * 2;
            float v00 = acc[i][j][0] + b0v, v01 = acc[i][j][1] + b0v;
            float v10 = acc[i][j][2] + b1v, v11 = acc[i][j][3] + b1v;
            if (MODE == 0) {
                ushort_t h0, l0, h1, l1;
                split2(hswish(v00), h0, l0);
                split2(hswish(v01), h1, l1);
                *(uint32_t*)&Chh[(size_t)r0 * NB + cb] = (uint32_t)h0 | ((uint32_t)h1 << 16);
                *(uint32_t*)&Chl[(size_t)r0 * NB + cb] = (uint32_t)l0 | ((uint32_t)l1 << 16);
                split2(hswish(v10), h0, l0);
                split2(hswish(v11), h1, l1);
                *(uint32_t*)&Chh[(size_t)r1 * NB + cb] = (uint32_t)h0 | ((uint32_t)h1 << 16);
                *(uint32_t*)&Chl[(size_t)r1 * NB + cb] = (uint32_t)l0 | ((uint32_t)l1 << 16);
            } else if (MODE == 1) {
                size_t o0 = (size_t)r0 * NB + cb;
                size_t o1 = (size_t)r1 * NB + cb;
                float2 rr0 = *(const float2*)&resid[o0];
                float2 rr1 = *(const float2*)&resid[o1];
                *(float2*)&Cf[o0] = make_float2(v00 + rr0.x, v01 + rr0.y);
                *(float2*)&Cf[o1] = make_float2(v10 + rr1.x, v11 + rr1.y);
            } else if (MODE == 2) {
                float vs[4] = {v00, v01, v10, v11};
#pragma unroll
                for (int q = 0; q < 4; q++) {
                    int col = cb + (q & 1);
                    int r = (q < 2) ? r0 : r1;
                    int win = col / NTOKP, tok = col % NTOKP;
                    if (tok < NTOK) {
                        int b = win >> 4, wy = (win >> 2) & 3, wx = win & 3;
                        int iy = tok / WS, ix = tok % WS;
                        size_t o = (size_t)r * NTOT + (size_t)b * HW
                                 + (wy * WS + iy) * RES + (wx * WS + ix);
                        Cf[o] = Cf[o] + vs[q];
                    }
                }
            } else {
                int b = cb / HW, pos = cb % HW;
                size_t o0 = (size_t)r0 * NB + cb;
                size_t o1 = (size_t)r1 * NB + cb;
                float2 rr0 = *(const float2*)&resid[o0];
                float2 rr1 = *(const float2*)&resid[o1];
                *(float2*)&Cf[((size_t)b * ED + r0) * HW + pos] =
                    make_float2(v00 + rr0.x, v01 + rr0.y);
                *(float2*)&Cf[((size_t)b * ED + r1) * HW + pos] =
                    make_float2(v10 + rr1.x, v11 + rr1.y);
            }
        }
    }
}

// ---------------------------------------------------------------------------
// Cascaded window attention (vectorized, coalesced output stores)
// ---------------------------------------------------------------------------
#define SP_OFF   0
#define Y_OFF    (SP_OFF + 49 * 68)
#define KT_OFF   (Y_OFF + 96 * 52)
#define QT_OFF   (KT_OFF + 49 * 20)
#define ATT_OFF  (QT_OFF + 49 * 20)
#define WSM_OFF  (ATT_OFF + 49 * 52)
#define BSM_OFF  (WSM_OFF + 96 * 68)
#define BIA_OFF  (BSM_OFF + 96)
#define ATTN_SMEM_FLOATS (BIA_OFF + 64)
#define ATTN_SMEM_BYTES  (ATTN_SMEM_FLOATS * 4)

__global__ void __launch_bounds__(256) attn_kernel(
    const float* __restrict__ xin,
    const float* __restrict__ qkv_w,
    const float* __restrict__ qkv_b,
    const float* __restrict__ w7, const float* __restrict__ b7,
    const float* __restrict__ w5, const float* __restrict__ b5,
    const float* __restrict__ w3, const float* __restrict__ b3,
    const float* __restrict__ attn_bias,
    ushort_t* __restrict__ oh, ushort_t* __restrict__ ol)
{
    extern __shared__ float smem[];
    float* spT = smem + SP_OFF;
    float* y   = smem + Y_OFF;
    float* kT  = smem + KT_OFF;
    float* qcT = smem + QT_OFF;
    float* att = smem + ATT_OFF;
    float* wsm = smem + WSM_OFF;
    float* bsm = smem + BSM_OFF;
    float* bia = smem + BIA_OFF;

    int w = blockIdx.x;
    int b = w >> 4, wy = (w >> 2) & 3, wx = w & 3;
    int t = threadIdx.x;
    int warp = t >> 5, lane = t & 31;

    for (int i = t; i < 96 * 3; i += 256)
        y[(i / 3) * 52 + 49 + i % 3] = 0.f;

    for (int head = 0; head < NH; head++) {
        for (int i = t; i < QKV_OUT * DHEAD; i += 256) {
            int m = i >> 6, c = i & 63;
            wsm[m * 68 + c] = qkv_w[head * QKV_OUT * DHEAD + i];
        }
        if (t < QKV_OUT) bsm[t] = qkv_b[head * QKV_OUT + t];
        if (t < NTOK)    bia[t] = attn_bias[head * NTOK + t];
        for (int i = t; i < DHEAD * NTOK; i += 256) {
            int c = i / NTOK, n = i % NTOK;
            int iy = n / WS, ix = n % WS;
            float xv = xin[(size_t)(head * DHEAD + c) * NTOT + (size_t)b * HW
                           + (wy * WS + iy) * RES + (wx * WS + ix)];
            spT[n * 68 + c] = (head == 0) ? xv : spT[n * 68 + c] + xv;
        }
        __syncthreads();

        // QKV
        for (int it = t; it < 13 * 96; it += 256) {
            int gq = it / 96, m = it % 96;
            int n0 = gq * 4;
            float a0 = bsm[m], a1 = a0, a2 = a0, a3 = a0;
            const float* wr = &wsm[m * 68];
#pragma unroll
            for (int c4 = 0; c4 < 16; c4++) {
                float4 wv = *(const float4*)&wr[c4 * 4];
                float4 s0 = *(const float4*)&spT[(n0 + 0) * 68 + c4 * 4];
                float4 s1 = *(const float4*)&spT[(n0 + 1) * 68 + c4 * 4];
                float4 s2 = *(const float4*)&spT[(n0 + 2) * 68 + c4 * 4];
                float4 s3 = *(const float4*)&spT[(n0 + 3) * 68 + c4 * 4];
                a0 += wv.x * s0.x + wv.y * s0.y + wv.z * s0.z + wv.w * s0.w;
                a1 += wv.x * s1.x + wv.y * s1.y + wv.z * s1.z + wv.w * s1.w;
                a2 += wv.x * s2.x + wv.y * s2.y + wv.z * s2.z + wv.w * s2.w;
                a3 += wv.x * s3.x + wv.y * s3.y + wv.z * s3.z + wv.w * s3.w;
            }
            float av[4] = {a0, a1, a2, a3};
#pragma unroll
            for (int j = 0; j < 4; j++) {
                int n = n0 + j;
                if (n < NTOK) {
                    y[m * 52 + n] = av[j];
                    if (m >= KD && m < 2 * KD) kT[n * 20 + m - KD] = av[j];
                }
            }
        }
        __syncthreads();

        // depthwise conv on q
        int ksz; const float* dw; const float* db;
        if (head == 0)      { ksz = 7; dw = w7; db = b7; }
        else if (head == 1) { ksz = 5; dw = w5; db = b5; }
        else                { ksz = 3; dw = w3 + (head - 2) * KD * 9; db = b3 + (head - 2) * KD; }
        int pad = ksz >> 1;
        for (int it = t; it < KD * NTOK; it += 256) {
            int c = it / NTOK, n = it % NTOK;
            int iy = n / WS, ix = n % WS;
            float acc = db[c];
            const float* yr = &y[c * 52];
            const float* dwc = dw + c * ksz * ksz;
            for (int dy = 0; dy < ksz; dy++) {
                int yy = iy + dy - pad;
                if (yy < 0 || yy >= WS) continue;
                for (int dx = 0; dx < ksz; dx++) {
                    int xx = ix + dx - pad;
                    if (xx < 0 || xx >= WS) continue;
                    acc += yr[yy * WS + xx] * dwc[dy * ksz + dx];
                }
            }
            qcT[n * 20 + c] = acc;
        }
        __syncthreads();

        // scores
        for (int it = t; it < 49 * 52; it += 256) {
            int n = it / 52, m = it % 52;
            if (m >= NTOK) { att[it] = 0.f; continue; }
            const float* qr = &qcT[n * 20];
            const float* kr = &kT[m * 20];
            float acc = 0.f;
#pragma unroll
            for (int c4 = 0; c4 < 4; c4++) {
                float4 qv = *(const float4*)&qr[c4 * 4];
                float4 kv = *(const float4*)&kr[c4 * 4];
                acc += qv.x * kv.x + qv.y * kv.y + qv.z * kv.z + qv.w * kv.w;
            }
            int ny = n / WS, nx = n % WS, my = m / WS, mx = m % WS;
            att[it] = acc * 0.25f + bia[abs(ny - my) * WS + abs(nx - mx)];
        }
        __syncthreads();

        // softmax: warp per row
        for (int r = warp; r < NTOK; r += 8) {
            float v0 = att[r * 52 + lane];
            float v1 = (lane + 32 < NTOK) ? att[r * 52 + lane + 32] : -1e30f;
            float mx = fmaxf(v0, v1);
#pragma unroll
            for (int s = 16; s; s >>= 1) mx = fmaxf(mx, __shfl_xor_sync(~0u, mx, s));
            float e0 = expf(v0 - mx);
            float e1 = (lane + 32 < NTOK) ? expf(v1 - mx) : 0.f;
            float sum = e0 + e1;
#pragma unroll
            for (int s = 16; s; s >>= 1) sum += __shfl_xor_sync(~0u, sum, s);
            float inv = 1.f / sum;
            att[r * 52 + lane] = e0 * inv;
            if (lane + 32 < NTOK) att[r * 52 + lane + 32] = e1 * inv;
        }
        __syncthreads();

        // AV: it = dg*49 + n, n fastest -> coalesced stores per d
        size_t obase = (size_t)(head * DHEAD) * NPROJ + (size_t)w * NTOKP;
        for (int it = t; it < 16 * NTOK; it += 256) {
            int dg = it / NTOK, n = it % NTOK;
            int d0 = dg * 4;
            float a0 = 0.f, a1 = 0.f, a2 = 0.f, a3 = 0.f;
            const float* ar = &att[n * 52];
#pragma unroll
            for (int m4 = 0; m4 < 13; m4++) {
                float4 av = *(const float4*)&ar[m4 * 4];
                float4 v0 = *(const float4*)&y[(32 + d0 + 0) * 52 + m4 * 4];
                float4 v1 = *(const float4*)&y[(32 + d0 + 1) * 52 + m4 * 4];
                float4 v2 = *(const float4*)&y[(32 + d0 + 2) * 52 + m4 * 4];
                float4 v3 = *(const float4*)&y[(32 + d0 + 3) * 52 + m4 * 4];
                a0 += av.x * v0.x + av.y * v0.y + av.z * v0.z + av.w * v0.w;
                a1 += av.x * v1.x + av.y * v1.y + av.z * v1.z + av.w * v1.w;
                a2 += av.x * v2.x + av.y * v2.y + av.z * v2.z + av.w * v2.w;
                a3 += av.x * v3.x + av.y * v3.y + av.z * v3.z + av.w * v3.w;
            }
            float av4[4] = {a0, a1, a2, a3};
#pragma unroll
            for (int jj = 0; jj < 4; jj++) {
                int d = d0 + jj;
                spT[n * 68 + d] = av4[jj];
                ushort_t hh, ll;
                split2(hswish(av4[jj]), hh, ll);
                oh[obase + (size_t)d * NPROJ + n] = hh;
                ol[obase + (size_t)d * NPROJ + n] = ll;
            }
        }
        for (int it = t; it < DHEAD * (NTOKP - NTOK); it += 256) {
            int p = it / DHEAD, d = it % DHEAD;
            oh[obase + (size_t)d * NPROJ + NTOK + p] = 0;
            ol[obase + (size_t)d * NPROJ + NTOK + p] = 0;
        }
        __syncthreads();
    }
}

// ---------------------------------------------------------------------------
extern "C" void kernel_launch(void* const* d_in, const int* in_sizes, int n_in,
                              void* d_out, int out_size)
{
    const float* x        = (const float*)d_in[0];
    const float* dw0_w    = (const float*)d_in[1];
    const float* dw0_b    = (const float*)d_in[2];
    const float* ffn0_w1  = (const float*)d_in[3];
    const float* ffn0_b1  = (const float*)d_in[4];
    const float* ffn0_w2  = (const float*)d_in[5];
    const float* ffn0_b2  = (const float*)d_in[6];
    const float* qkv_w    = (const float*)d_in[7];
    const float* qkv_b    = (const float*)d_in[8];
    const float* dwq_w7   = (const float*)d_in[9];
    const float* dwq_b7   = (const float*)d_in[10];
    const float* dwq_w5   = (const float*)d_in[11];
    const float* dwq_b5   = (const float*)d_in[12];
    const float* dwq_w3   = (const float*)d_in[13];
    const float* dwq_b3   = (const float*)d_in[14];
    const float* attn_bias= (const float*)d_in[15];
    const float* proj_w   = (const float*)d_in[16];
    const float* proj_b   = (const float*)d_in[17];
    const float* dw1_w    = (const float*)d_in[18];
    const float* dw1_b    = (const float*)d_in[19];
    const float* ffn1_w1  = (const float*)d_in[20];
    const float* ffn1_b1  = (const float*)d_in[21];
    const float* ffn1_w2  = (const float*)d_in[22];
    const float* ffn1_b2  = (const float*)d_in[23];

    float *paf, *pbf;
    ushort_t *pah, *pal, *phh, *phl, *pch, *pcl;
    ushort_t *pw1h, *pw1l, *pw2h, *pw2l, *pw1bh, *pw1bl, *pw2bh, *pw2bl, *ppjh, *ppjl;
    cudaGetSymbolAddress((void**)&paf, g_af);
    cudaGetSymbolAddress((void**)&pbf, g_bf);
    cudaGetSymbolAddress((void**)&pah, g_ah);
    cudaGetSymbolAddress((void**)&pal, g_al);
    cudaGetSymbolAddress((void**)&phh, g_hh);
    cudaGetSymbolAddress((void**)&phl, g_hl);
    cudaGetSymbolAddress((void**)&pch, g_ch);
    cudaGetSymbolAddress((void**)&pcl, g_cl);
    cudaGetSymbolAddress((void**)&pw1h, g_w1h);
    cudaGetSymbolAddress((void**)&pw1l, g_w1l);
    cudaGetSymbolAddress((void**)&pw2h, g_w2h);
    cudaGetSymbolAddress((void**)&pw2l, g_w2l);
    cudaGetSymbolAddress((void**)&pw1bh, g_w1bh);
    cudaGetSymbolAddress((void**)&pw1bl, g_w1bl);
    cudaGetSymbolAddress((void**)&pw2bh, g_w2bh);
    cudaGetSymbolAddress((void**)&pw2bl, g_w2bl);
    cudaGetSymbolAddress((void**)&ppjh, g_pjh);
    cudaGetSymbolAddress((void**)&ppjl, g_pjl);

    cudaFuncSetAttribute(attn_kernel, cudaFuncAttributeMaxDynamicSharedMemorySize, ATTN_SMEM_BYTES);
    cudaFuncSetAttribute(gemm_cp_kernel<0>, cudaFuncAttributeMaxDynamicSharedMemorySize, 65536);
    cudaFuncSetAttribute(gemm_cp_kernel<1>, cudaFuncAttributeMaxDynamicSharedMemorySize, 65536);
    cudaFuncSetAttribute(gemm_cp_kernel<2>, cudaFuncAttributeMaxDynamicSharedMemorySize, 65536);
    cudaFuncSetAttribute(gemm_cp_kernel<3>, cudaFuncAttributeMaxDynamicSharedMemorySize, 65536);

    // Weight pre-split
    pack_weights_kernel<<<2048, 256>>>(ffn0_w1, pw1h, pw1l, 1024 * 512);
    pack_weights_kernel<<<2048, 256>>>(ffn0_w2, pw2h, pw2l, 512 * 1024);
    pack_weights_kernel<<<2048, 256>>>(ffn1_w1, pw1bh, pw1bl, 1024 * 512);
    pack_weights_kernel<<<2048, 256>>>(ffn1_w2, pw2bh, pw2bl, 512 * 1024);
    pack_weights_kernel<<<1024, 256>>>(proj_w, ppjh, ppjl, 512 * 512);

    dim3 dwgrid((HW + 255) / 256, BATCH * ED);

    dwconv_res_kernel<false><<<dwgrid, 256>>>(x, dw0_w, dw0_b, paf, pah, pal);
    gemm_cp_kernel<0><<<dim3(NTOT / 128, 8), 256, 65536>>>(
        pw1h, pw1l, pah, pal, ffn0_b1, nullptr, nullptr, phh, phl, 1024, NTOT, 512);
    gemm_cp_kernel<1><<<dim3(NTOT / 128, 4), 256, 65536>>>(
        pw2h, pw2l, phh, phl, ffn0_b2, paf, pbf, nullptr, nullptr, 512, NTOT, 1024);
    attn_kernel<<<NW_TOT, 256, ATTN_SMEM_BYTES>>>(pbf, qkv_w, qkv_b, dwq_w7, dwq_b7,
        dwq_w5, dwq_b5, dwq_w3, dwq_b3, attn_bias, pch, pcl);
    gemm_cp_kernel<2><<<dim3(NPROJ / 128, 4), 256, 65536>>>(
        ppjh, ppjl, pch, pcl, proj_b, nullptr, pbf, nullptr, nullptr, 512, NPROJ, 512);
    dwconv_res_kernel<true><<<dwgrid, 256>>>(pbf, dw1_w, dw1_b, paf, pah, pal);
    gemm_cp_kernel<0><<<dim3(NTOT / 128, 8), 256, 65536>>>(
        pw1bh, pw1bl, pah, pal, ffn1_b1, nullptr, nullptr, phh, phl, 1024, NTOT, 512);
    gemm_cp_kernel<3><<<dim3(NTOT / 128, 4), 256, 65536>>>(
        pw2bh, pw2bl, phh, phl, ffn1_b2, paf, (float*)d_out, nullptr, nullptr, 512, NTOT, 1024);
}